// round 13
// baseline (speedup 1.0000x reference)
#include <cuda_runtime.h>
#include <cuda_bf16.h>
#include <math.h>
#include <stdint.h>

#define PI_F 3.14159265358979323846f
typedef __nv_bfloat16 bf16;

// ---------------- scratch ----------------
__device__ bf16 g_xh  [2048 * 512];
__device__ bf16 g_xl  [2048 * 512];
__device__ bf16 g_Wth [4 * 512 * 512];
__device__ bf16 g_Wtl [4 * 512 * 512];
__device__ bf16 g_Wph [128 * 512];
__device__ bf16 g_Wpl [128 * 512];
__device__ bf16 g_Hkh [2048 * 512];
__device__ bf16 g_Hkl [2048 * 512];
__device__ bf16 g_Hqh [2048 * 512];
__device__ bf16 g_Hql [2048 * 512];
__device__ bf16 g_Vh  [2048 * 512];
__device__ bf16 g_Vl  [2048 * 512];
__device__ bf16 g_CSkh[2048 * 128];
__device__ bf16 g_CSkl[2048 * 128];
__device__ bf16 g_CSqh[2048 * 128];
__device__ bf16 g_CSql[2048 * 128];
__device__ bf16 g_CSkTh[32 * 128 * 64];
__device__ bf16 g_CSkTl[32 * 128 * 64];
__device__ bf16 g_Ach [32 * 64 * 64];
__device__ bf16 g_Acl [32 * 64 * 64];
__device__ float g_S  [32 * 128 * 512];
__device__ bf16 g_Ph  [32 * 128 * 512];
__device__ bf16 g_Pl  [32 * 128 * 512];
__device__ float g_R  [2048 * 512];
__device__ bf16 g_LNh [2048 * 512];
__device__ bf16 g_LNl [2048 * 512];

// ================= PTX helpers =================
__device__ __forceinline__ uint32_t smem_u32(const void* p) {
    uint32_t a;
    asm("{ .reg .u64 t; cvta.to.shared.u64 t, %1; cvt.u32.u64 %0, t; }" : "=r"(a) : "l"(p));
    return a;
}
__device__ __forceinline__ void cp16(uint32_t dst, const void* src) {
    asm volatile("cp.async.cg.shared.global [%0], [%1], 16;" :: "r"(dst), "l"(src));
}
__device__ __forceinline__ void ldx4(uint32_t* r, uint32_t addr) {
    asm volatile("ldmatrix.sync.aligned.m8n8.x4.shared.b16 {%0,%1,%2,%3}, [%4];"
        : "=r"(r[0]), "=r"(r[1]), "=r"(r[2]), "=r"(r[3]) : "r"(addr));
}
__device__ __forceinline__ void ldx4t(uint32_t* r, uint32_t addr) {
    asm volatile("ldmatrix.sync.aligned.m8n8.x4.trans.shared.b16 {%0,%1,%2,%3}, [%4];"
        : "=r"(r[0]), "=r"(r[1]), "=r"(r[2]), "=r"(r[3]) : "r"(addr));
}
__device__ __forceinline__ void mma16816(float* c, const uint32_t* a,
                                         uint32_t b0, uint32_t b1) {
    asm volatile("mma.sync.aligned.m16n8k16.row.col.f32.bf16.bf16.f32 "
        "{%0,%1,%2,%3}, {%4,%5,%6,%7}, {%8,%9}, {%0,%1,%2,%3};"
        : "+f"(c[0]), "+f"(c[1]), "+f"(c[2]), "+f"(c[3])
        : "r"(a[0]), "r"(a[1]), "r"(a[2]), "r"(a[3]), "r"(b0), "r"(b1));
}
__device__ __forceinline__ void bsplit2(float v0, float v1, bf16* hd, bf16* ld) {
    __nv_bfloat162 h, l;
    h.x = __float2bfloat16(v0); h.y = __float2bfloat16(v1);
    l.x = __float2bfloat16(v0 - __bfloat162float(h.x));
    l.y = __float2bfloat16(v1 - __bfloat162float(h.y));
    *(__nv_bfloat162*)hd = h; *(__nv_bfloat162*)ld = l;
}
#define CPA_COMMIT() asm volatile("cp.async.commit_group;" ::: "memory")
#define CPA_WAIT1()  asm volatile("cp.async.wait_group 1;" ::: "memory")
#define CPA_WAIT0()  asm volatile("cp.async.wait_group 0;" ::: "memory")

// ================= XW / OUT GEMM: 64x64 tile, 128 thr, 4 warps (2m x 2n) ====
// MODE 0: XW (split bf16 out, gelu z<2, bias); MODE 1: OUT (fp32 + resid + bias)
static constexpr int XA_ARR = 64 * 80;
static constexpr int XB_OFF = 2 * XA_ARR;
static constexpr int XB_ARR = 64 * 80;
static constexpr int X_BUF  = XB_OFF + 2 * XB_ARR;  // 20480
static constexpr int X_SMEM = 2 * X_BUF;            // 40960

template<int MODE>
__global__ __launch_bounds__(128, 4)
void mma_gemm(const bf16* __restrict__ Ah, const bf16* __restrict__ Al,
              const bf16* __restrict__ Wth, const bf16* __restrict__ Wtl,
              const float* __restrict__ b0, const float* __restrict__ b1,
              const float* __restrict__ b2, const float* __restrict__ resid,
              bf16* __restrict__ O0h, bf16* __restrict__ O0l,
              bf16* __restrict__ O1h, bf16* __restrict__ O1l,
              bf16* __restrict__ O2h, bf16* __restrict__ O2l,
              float* __restrict__ Cout)
{
    extern __shared__ __align__(128) char smem[];
    const uint32_t sb = smem_u32(smem);
    const int tid = threadIdx.x, wid = tid >> 5, lane = tid & 31;
    const int row0 = blockIdx.y * 64, col0 = blockIdx.x * 64;
    const int z = (MODE == 0) ? (int)blockIdx.z : 0;
    const bf16* Bh = Wth + (long)z * 262144;
    const bf16* Bl = Wtl + (long)z * 262144;
    const float* bias = (z == 0) ? b0 : (z == 1 ? b1 : b2);
    const bool gelu = (MODE == 0) && (z < 2);
    bf16* Oh = (z == 0) ? O0h : (z == 1 ? O1h : O2h);
    bf16* Ol = (z == 0) ? O0l : (z == 1 ? O1l : O2l);

    const int wm = (wid & 1) * 32, wn = (wid >> 1) * 32;
    float acc[2][4][4];
    #pragma unroll
    for (int i = 0; i < 2; i++)
        #pragma unroll
        for (int j = 0; j < 4; j++)
            #pragma unroll
            for (int e = 0; e < 4; e++) acc[i][j][e] = 0.0f;

    const int g = lane >> 3, wr = lane & 7;
    const int fRow = wr + (g & 1) * 8, fK = (g >> 1) * 8;

    auto load_chunk = [&](int ch, int b) {
        const int k0 = ch * 32;
        const uint32_t base = sb + b * X_BUF;
        #pragma unroll
        for (int l = 0; l < 4; l++) {
            const int idx = tid + l * 128;
            const int arr = idx >> 8, rr = (idx >> 2) & 63, s = idx & 3;
            cp16(base + arr * XA_ARR + rr * 80 + s * 16,
                 (arr ? Al : Ah) + (long)(row0 + rr) * 512 + k0 + s * 8);
        }
        #pragma unroll
        for (int l = 0; l < 4; l++) {
            const int idx = tid + l * 128;
            const int arr = idx >> 8, rr = (idx >> 2) & 63, s = idx & 3;
            cp16(base + XB_OFF + arr * XB_ARR + rr * 80 + s * 16,
                 (arr ? Bl : Bh) + (long)(col0 + rr) * 512 + k0 + s * 8);
        }
        CPA_COMMIT();
    };

    load_chunk(0, 0);
    for (int ch = 0; ch < 16; ch++) {
        const int b = ch & 1;
        if (ch < 15) { load_chunk(ch + 1, b ^ 1); CPA_WAIT1(); }
        else CPA_WAIT0();
        __syncthreads();
        const uint32_t base = sb + b * X_BUF;
        #pragma unroll
        for (int ks = 0; ks < 2; ks++) {
            uint32_t ahf[2][4], alf[2][4], bb[2][4];
            #pragma unroll
            for (int mt = 0; mt < 2; mt++) {
                const uint32_t ra = base + (wm + mt * 16 + fRow) * 80 + (ks * 16 + fK) * 2;
                ldx4(ahf[mt], ra);
                ldx4(alf[mt], ra + XA_ARR);
            }
            #pragma unroll
            for (int nt = 0; nt < 2; nt++) {
                const uint32_t rb = base + XB_OFF + (wn + nt * 16 + fRow) * 80 + (ks * 16 + fK) * 2;
                ldx4(bb[nt], rb);
            }
            #pragma unroll
            for (int mt = 0; mt < 2; mt++)
                #pragma unroll
                for (int nt = 0; nt < 2; nt++) {
                    mma16816(acc[mt][nt*2],   ahf[mt], bb[nt][0], bb[nt][2]);
                    mma16816(acc[mt][nt*2+1], ahf[mt], bb[nt][1], bb[nt][3]);
                    mma16816(acc[mt][nt*2],   alf[mt], bb[nt][0], bb[nt][2]);
                    mma16816(acc[mt][nt*2+1], alf[mt], bb[nt][1], bb[nt][3]);
                }
            #pragma unroll
            for (int nt = 0; nt < 2; nt++) {
                const uint32_t rb = base + XB_OFF + XB_ARR + (wn + nt * 16 + fRow) * 80 + (ks * 16 + fK) * 2;
                ldx4(bb[nt], rb);
            }
            #pragma unroll
            for (int mt = 0; mt < 2; mt++)
                #pragma unroll
                for (int nt = 0; nt < 2; nt++) {
                    mma16816(acc[mt][nt*2],   ahf[mt], bb[nt][0], bb[nt][2]);
                    mma16816(acc[mt][nt*2+1], ahf[mt], bb[nt][1], bb[nt][3]);
                }
        }
        __syncthreads();
    }

    #pragma unroll
    for (int mt = 0; mt < 2; mt++)
        #pragma unroll
        for (int h = 0; h < 2; h++) {
            const int row = row0 + wm + mt * 16 + h * 8 + (lane >> 2);
            #pragma unroll
            for (int n8 = 0; n8 < 4; n8++) {
                const int col = col0 + wn + n8 * 8 + (lane & 3) * 2;
                float v0 = acc[mt][n8][h * 2 + 0];
                float v1 = acc[mt][n8][h * 2 + 1];
                const float2 bq = *(const float2*)&bias[col];
                v0 += bq.x; v1 += bq.y;
                if (MODE == 0) {
                    if (gelu) {
                        v0 = 0.5f * v0 * (1.0f + erff(v0 * 0.70710678118654752f));
                        v1 = 0.5f * v1 * (1.0f + erff(v1 * 0.70710678118654752f));
                    }
                    bsplit2(v0, v1, Oh + (long)row * 512 + col, Ol + (long)row * 512 + col);
                } else {
                    const float2 r2 = *(const float2*)&resid[(long)row * 512 + col];
                    float2 o; o.x = v0 + r2.x; o.y = v1 + r2.y;
                    *(float2*)&Cout[(long)row * 512 + col] = o;
                }
            }
        }
}

// ================= phase GEMM: 32x64 tile, 256 thr, split-K (2 groups) =====
static constexpr int PH_A    = 32 * 80;
static constexpr int PH_HALF = 2 * PH_A + 2 * 64 * 80;
static constexpr int PH_STG  = 2 * PH_HALF;
static constexpr int P_SMEM  = 2 * PH_STG;   // 61440

__global__ __launch_bounds__(256)
void phase_mma(const bf16* __restrict__ Hkh, const bf16* __restrict__ Hkl,
               const bf16* __restrict__ Hqh, const bf16* __restrict__ Hql,
               const bf16* __restrict__ Wph, const bf16* __restrict__ Wpl,
               const float* __restrict__ bk2, const float* __restrict__ bq2,
               bf16* __restrict__ CSkh, bf16* __restrict__ CSkl,
               bf16* __restrict__ CSqh, bf16* __restrict__ CSql,
               bf16* __restrict__ CSkTh, bf16* __restrict__ CSkTl)
{
    extern __shared__ __align__(128) char smem[];
    const uint32_t sb = smem_u32(smem);
    const int tid = threadIdx.x, wid = tid >> 5, lane = tid & 31;
    const int z = blockIdx.z, row0 = blockIdx.y * 32;
    const bf16* Ah = z ? Hqh : Hkh;
    const bf16* Al = z ? Hql : Hkl;
    const bf16* Bh = Wph + (long)z * 64 * 512;
    const bf16* Bl = Wpl + (long)z * 64 * 512;
    const float* bias = z ? bq2 : bk2;

    const int grp = wid >> 2;
    const int wid2 = wid & 3;
    const int wm = (wid2 & 1) * 16, wn = (wid2 >> 1) * 32;
    float acc[4][4];
    #pragma unroll
    for (int j = 0; j < 4; j++)
        #pragma unroll
        for (int e = 0; e < 4; e++) acc[j][e] = 0.0f;

    const int g = lane >> 3, wr = lane & 7;
    const int fRow = wr + (g & 1) * 8, fK = (g >> 1) * 8;

    auto load_chunk = [&](int ch) {
        const int k0 = ch * 32;
        const uint32_t base = sb + (ch & 1) * PH_STG;
        #pragma unroll
        for (int l = 0; l < 2; l++) {
            const int idx = tid + l * 256;
            const int hf = idx >> 8, ii = idx & 255;
            const int arr = ii >> 7, pos = ii & 127, rr = pos >> 2, s = pos & 3;
            cp16(base + hf * PH_HALF + arr * PH_A + rr * 80 + s * 16,
                 (arr ? Al : Ah) + (long)(row0 + rr) * 512 + hf * 256 + k0 + s * 8);
        }
        #pragma unroll
        for (int l = 0; l < 4; l++) {
            const int idx = tid + l * 256;
            const int hf = idx >> 9, ii = idx & 511;
            const int arr = ii >> 8, pos = ii & 255, rr = pos >> 2, s = pos & 3;
            cp16(base + hf * PH_HALF + 2 * PH_A + arr * 5120 + rr * 80 + s * 16,
                 (arr ? Bl : Bh) + (long)rr * 512 + hf * 256 + k0 + s * 8);
        }
        CPA_COMMIT();
    };

    load_chunk(0);
    for (int ch = 0; ch < 8; ch++) {
        if (ch < 7) { load_chunk(ch + 1); CPA_WAIT1(); }
        else CPA_WAIT0();
        __syncthreads();
        const uint32_t hbase = sb + (ch & 1) * PH_STG + grp * PH_HALF;
        #pragma unroll
        for (int ks = 0; ks < 2; ks++) {
            uint32_t ahf[4], alf[4], bb[2][4];
            {
                const uint32_t ra = hbase + (wm + fRow) * 80 + (ks * 16 + fK) * 2;
                ldx4(ahf, ra);
                ldx4(alf, ra + PH_A);
            }
            #pragma unroll
            for (int nt = 0; nt < 2; nt++) {
                const uint32_t rb = hbase + 2 * PH_A + (wn + nt * 16 + fRow) * 80 + (ks * 16 + fK) * 2;
                ldx4(bb[nt], rb);
            }
            #pragma unroll
            for (int nt = 0; nt < 2; nt++) {
                mma16816(acc[nt*2],   ahf, bb[nt][0], bb[nt][2]);
                mma16816(acc[nt*2+1], ahf, bb[nt][1], bb[nt][3]);
                mma16816(acc[nt*2],   alf, bb[nt][0], bb[nt][2]);
                mma16816(acc[nt*2+1], alf, bb[nt][1], bb[nt][3]);
            }
            #pragma unroll
            for (int nt = 0; nt < 2; nt++) {
                const uint32_t rb = hbase + 2 * PH_A + 5120 + (wn + nt * 16 + fRow) * 80 + (ks * 16 + fK) * 2;
                ldx4(bb[nt], rb);
            }
            #pragma unroll
            for (int nt = 0; nt < 2; nt++) {
                mma16816(acc[nt*2],   ahf, bb[nt][0], bb[nt][2]);
                mma16816(acc[nt*2+1], ahf, bb[nt][1], bb[nt][3]);
            }
        }
        __syncthreads();
    }

    float* red = (float*)smem;
    #pragma unroll
    for (int j = 0; j < 4; j++)
        *(float4*)&red[tid * 16 + j * 4] = *(float4*)acc[j];
    __syncthreads();
    if (tid < 128) {
        #pragma unroll
        for (int j = 0; j < 4; j++) {
            float4 o = *(float4*)&red[(tid + 128) * 16 + j * 4];
            acc[j][0] += o.x; acc[j][1] += o.y; acc[j][2] += o.z; acc[j][3] += o.w;
        }
        #pragma unroll
        for (int h = 0; h < 2; h++) {
            const int row = row0 + wm + h * 8 + (lane >> 2);
            #pragma unroll
            for (int j = 0; j < 4; j++) {
                const int n = wn + (j >> 1) * 16 + (j & 1) * 8 + (lane & 3) * 2;
                float v0 = acc[j][h * 2 + 0] + bias[n];
                float v1 = acc[j][h * 2 + 1] + bias[n + 1];
                float p0 = tanhf(v0) * PI_F, p1 = tanhf(v1) * PI_F;
                float c0, s0, c1, s1;
                sincosf(p0, &s0, &c0);
                sincosf(p1, &s1, &c1);
                bf16* Rh = z ? CSqh : CSkh;
                bf16* Rl = z ? CSql : CSkl;
                const long rb_ = (long)row * 128;
                bsplit2(c0, c1, Rh + rb_ + n,      Rl + rb_ + n);
                bsplit2(s0, s1, Rh + rb_ + n + 64, Rl + rb_ + n + 64);
                if (!z) {
                    const int c = row >> 6, ro = row & 63;
                    const long t0 = (long)c * 8192 + (long)n * 64 + ro;
                    bf16 h0 = __float2bfloat16(c0);
                    bf16 h1 = __float2bfloat16(c1);
                    bf16 h2 = __float2bfloat16(s0);
                    bf16 h3 = __float2bfloat16(s1);
                    CSkTh[t0]        = h0;
                    CSkTh[t0 + 64]   = h1;
                    CSkTh[t0 + 4096] = h2;
                    CSkTh[t0 + 4160] = h3;
                    CSkTl[t0]        = __float2bfloat16(c0 - __bfloat162float(h0));
                    CSkTl[t0 + 64]   = __float2bfloat16(c1 - __bfloat162float(h1));
                    CSkTl[t0 + 4096] = __float2bfloat16(s0 - __bfloat162float(h2));
                    CSkTl[t0 + 4160] = __float2bfloat16(s1 - __bfloat162float(h3));
                }
            }
        }
    }
}

// ================= S + Ac combined launch ==================================
static constexpr int S_AARR = 128 * 80;
static constexpr int S_BOFF = 2 * S_AARR;
static constexpr int S_BARR = 32 * 144;
static constexpr int S_BUF  = S_BOFF + 2 * S_BARR;
static constexpr int SAC_SMEM = 2 * S_BUF;
static constexpr int AC_AARR = 64 * 80;
static constexpr int AC_BOFF = 2 * AC_AARR;
static constexpr int AC_BUF  = 2 * AC_BOFF;

__global__ __launch_bounds__(256)
void sac_mma(const bf16* __restrict__ CSkTh, const bf16* __restrict__ CSkTl,
             const bf16* __restrict__ Vh, const bf16* __restrict__ Vl,
             const bf16* __restrict__ CSqh, const bf16* __restrict__ CSql,
             const bf16* __restrict__ CSkh, const bf16* __restrict__ CSkl,
             float* __restrict__ S, bf16* __restrict__ Ach, bf16* __restrict__ Acl)
{
    extern __shared__ __align__(128) char smem[];
    const uint32_t sb = smem_u32(smem);
    const int tid = threadIdx.x, wid = tid >> 5, lane = tid & 31;
    const int c = blockIdx.z;
    const int g = lane >> 3, wr = lane & 7;
    const int fRow = wr + (g & 1) * 8, fK = (g >> 1) * 8;
    const int tK = fRow, tN = (g >> 1) * 8;

    if (blockIdx.x < 8) {
        const int col0 = blockIdx.x * 64;
        const int wm = (wid & 3) * 32, wn = (wid >> 2) * 32;
        float acc[2][4][4];
        #pragma unroll
        for (int i = 0; i < 2; i++)
            #pragma unroll
            for (int j = 0; j < 4; j++)
                #pragma unroll
                for (int e = 0; e < 4; e++) acc[i][j][e] = 0.0f;

        auto load_chunk = [&](int ch, int b) {
            const int k0 = ch * 32;
            const uint32_t base = sb + b * S_BUF;
            #pragma unroll
            for (int l = 0; l < 4; l++) {
                const int idx = tid + l * 256;
                const int arr = idx >> 9, rr = (idx >> 2) & 127, s = idx & 3;
                cp16(base + arr * S_AARR + rr * 80 + s * 16,
                     (arr ? CSkTl : CSkTh) + (long)c * 8192 + (long)rr * 64 + k0 + s * 8);
            }
            #pragma unroll
            for (int l = 0; l < 2; l++) {
                const int idx = tid + l * 256;
                const int arr = idx >> 8, rr = (idx >> 3) & 31, s = idx & 7;
                cp16(base + S_BOFF + arr * S_BARR + rr * 144 + s * 16,
                     (arr ? Vl : Vh) + ((long)c * 64 + k0 + rr) * 512 + col0 + s * 8);
            }
            CPA_COMMIT();
        };

        load_chunk(0, 0);
        load_chunk(1, 1);
        for (int ch = 0; ch < 2; ch++) {
            if (ch == 0) CPA_WAIT1(); else CPA_WAIT0();
            __syncthreads();
            const uint32_t base = sb + ch * S_BUF;
            #pragma unroll
            for (int ks = 0; ks < 2; ks++) {
                uint32_t ahf[2][4], alf[2][4], bb[2][4];
                #pragma unroll
                for (int mt = 0; mt < 2; mt++) {
                    const uint32_t ra = base + (wm + mt * 16 + fRow) * 80 + (ks * 16 + fK) * 2;
                    ldx4(ahf[mt], ra);
                    ldx4(alf[mt], ra + S_AARR);
                }
                #pragma unroll
                for (int nt = 0; nt < 2; nt++) {
                    const uint32_t rb = base + S_BOFF + (ks * 16 + tK) * 144 + (wn + nt * 16 + tN) * 2;
                    ldx4t(bb[nt], rb);
                }
                #pragma unroll
                for (int mt = 0; mt < 2; mt++)
                    #pragma unroll
                    for (int nt = 0; nt < 2; nt++) {
                        mma16816(acc[mt][nt*2],   ahf[mt], bb[nt][0], bb[nt][1]);
                        mma16816(acc[mt][nt*2+1], ahf[mt], bb[nt][2], bb[nt][3]);
                        mma16816(acc[mt][nt*2],   alf[mt], bb[nt][0], bb[nt][1]);
                        mma16816(acc[mt][nt*2+1], alf[mt], bb[nt][2], bb[nt][3]);
                    }
                #pragma unroll
                for (int nt = 0; nt < 2; nt++) {
                    const uint32_t rb = base + S_BOFF + S_BARR + (ks * 16 + tK) * 144 + (wn + nt * 16 + tN) * 2;
                    ldx4t(bb[nt], rb);
                }
                #pragma unroll
                for (int mt = 0; mt < 2; mt++)
                    #pragma unroll
                    for (int nt = 0; nt < 2; nt++) {
                        mma16816(acc[mt][nt*2],   ahf[mt], bb[nt][0], bb[nt][1]);
                        mma16816(acc[mt][nt*2+1], ahf[mt], bb[nt][2], bb[nt][3]);
                    }
            }
            __syncthreads();
        }

        #pragma unroll
        for (int mt = 0; mt < 2; mt++)
            #pragma unroll
            for (int h = 0; h < 2; h++) {
                const int m = wm + mt * 16 + h * 8 + (lane >> 2);
                const long orow = (long)c * 65536 + (long)m * 512;
                #pragma unroll
                for (int n8 = 0; n8 < 4; n8++) {
                    const int col = col0 + wn + n8 * 8 + (lane & 3) * 2;
                    float2 o; o.x = acc[mt][n8][h*2+0]; o.y = acc[mt][n8][h*2+1];
                    *(float2*)&S[orow + col] = o;
                }
            }
    } else {
        const int wm = (wid & 1) * 32, wn = (wid >> 1) * 16;
        float acc[2][2][4];
        #pragma unroll
        for (int i = 0; i < 2; i++)
            #pragma unroll
            for (int j = 0; j < 2; j++)
                #pragma unroll
                for (int e = 0; e < 4; e++) acc[i][j][e] = 0.0f;

        auto load_chunk = [&](int ch, int b) {
            const int k0 = ch * 32;
            const uint32_t base = sb + b * AC_BUF;
            #pragma unroll
            for (int l = 0; l < 2; l++) {
                const int idx = tid + l * 256;
                const int arr = idx >> 8, rr = (idx >> 2) & 63, s = idx & 3;
                cp16(base + arr * AC_AARR + rr * 80 + s * 16,
                     (arr ? CSql : CSqh) + ((long)c * 64 + rr) * 128 + k0 + s * 8);
            }
            #pragma unroll
            for (int l = 0; l < 2; l++) {
                const int idx = tid + l * 256;
                const int arr = idx >> 8, rr = (idx >> 2) & 63, s = idx & 3;
                cp16(base + AC_BOFF + arr * AC_AARR + rr * 80 + s * 16,
                     (arr ? CSkl : CSkh) + ((long)c * 64 + rr) * 128 + k0 + s * 8);
            }
            CPA_COMMIT();
        };

        load_chunk(0, 0);
        for (int ch = 0; ch < 4; ch++) {
            const int b = ch & 1;
            if (ch < 3) { load_chunk(ch + 1, b ^ 1); CPA_WAIT1(); }
            else CPA_WAIT0();
            __syncthreads();
            const uint32_t base = sb + b * AC_BUF;
            #pragma unroll
            for (int ks = 0; ks < 2; ks++) {
                uint32_t ahf[2][4], alf[2][4], bb[4];
                #pragma unroll
                for (int mt = 0; mt < 2; mt++) {
                    const uint32_t ra = base + (wm + mt * 16 + fRow) * 80 + (ks * 16 + fK) * 2;
                    ldx4(ahf[mt], ra);
                    ldx4(alf[mt], ra + AC_AARR);
                }
                {
                    const uint32_t rb = base + AC_BOFF + (wn + fRow) * 80 + (ks * 16 + fK) * 2;
                    ldx4(bb, rb);
                }
                #pragma unroll
                for (int mt = 0; mt < 2; mt++) {
                    mma16816(acc[mt][0], ahf[mt], bb[0], bb[2]);
                    mma16816(acc[mt][1], ahf[mt], bb[1], bb[3]);
                    mma16816(acc[mt][0], alf[mt], bb[0], bb[2]);
                    mma16816(acc[mt][1], alf[mt], bb[1], bb[3]);
                }
                {
                    const uint32_t rb = base + AC_BOFF + AC_AARR + (wn + fRow) * 80 + (ks * 16 + fK) * 2;
                    ldx4(bb, rb);
                }
                #pragma unroll
                for (int mt = 0; mt < 2; mt++) {
                    mma16816(acc[mt][0], ahf[mt], bb[0], bb[2]);
                    mma16816(acc[mt][1], ahf[mt], bb[1], bb[3]);
                }
            }
            __syncthreads();
        }

        #pragma unroll
        for (int mt = 0; mt < 2; mt++)
            #pragma unroll
            for (int h = 0; h < 2; h++) {
                const int row = wm + mt * 16 + h * 8 + (lane >> 2);
                #pragma unroll
                for (int n8 = 0; n8 < 2; n8++) {
                    const int col = wn + n8 * 8 + (lane & 3) * 2;
                    float v0 = (col     <= row) ? acc[mt][n8][h*2+0] : 0.0f;
                    float v1 = (col + 1 <= row) ? acc[mt][n8][h*2+1] : 0.0f;
                    const long o = (long)c * 4096 + (long)row * 64 + col;
                    bsplit2(v0, v1, Ach + o, Acl + o);
                }
            }
    }
}

// ================= R GEMM: M64,N64,K192, 128 thr ===========================
static constexpr int R_AARR = 64 * 80;
static constexpr int R_BOFF = 2 * R_AARR;
static constexpr int R_BARR = 32 * 144;
static constexpr int R_BUF  = R_BOFF + 2 * R_BARR;
static constexpr int R_SMEM = 3 * R_BUF;

__global__ __launch_bounds__(128)
void r_mma(const bf16* __restrict__ CSqh, const bf16* __restrict__ CSql,
           const bf16* __restrict__ Ach, const bf16* __restrict__ Acl,
           const bf16* __restrict__ Ph, const bf16* __restrict__ Pl,
           const bf16* __restrict__ Vh, const bf16* __restrict__ Vl,
           float* __restrict__ Out)
{
    extern __shared__ __align__(128) char smem[];
    const uint32_t sb = smem_u32(smem);
    const int tid = threadIdx.x, wid = tid >> 5, lane = tid & 31;
    const int c = blockIdx.z, col0 = blockIdx.x * 64;
    const int wm = (wid & 1) * 32, wn = (wid >> 1) * 32;
    const int g = lane >> 3, wr = lane & 7;
    const int fRow = wr + (g & 1) * 8, fK = (g >> 1) * 8;
    const int tK = fRow, tN = (g >> 1) * 8;

    float acc[2][4][4];
    #pragma unroll
    for (int i = 0; i < 2; i++)
        #pragma unroll
        for (int j = 0; j < 4; j++)
            #pragma unroll
            for (int e = 0; e < 4; e++) acc[i][j][e] = 0.0f;

    auto load_chunk = [&](int ch) {
        const uint32_t base = sb + (ch % 3) * R_BUF;
        const bf16 *aH, *aL, *bH, *bL;
        int ldA, k0;
        long rowB;
        if (ch < 4) {
            aH = CSqh + (long)c * 8192; aL = CSql + (long)c * 8192;
            ldA = 128; k0 = ch * 32;
            bH = Ph; bL = Pl; rowB = (long)c * 128 + ch * 32;
        } else {
            aH = Ach + (long)c * 4096; aL = Acl + (long)c * 4096;
            ldA = 64; k0 = (ch - 4) * 32;
            bH = Vh; bL = Vl; rowB = (long)c * 64 + (ch - 4) * 32;
        }
        #pragma unroll
        for (int l = 0; l < 4; l++) {
            const int idx = tid + l * 128;
            const int arr = idx >> 8, rr = (idx >> 2) & 63, s = idx & 3;
            cp16(base + arr * R_AARR + rr * 80 + s * 16,
                 (arr ? aL : aH) + (long)rr * ldA + k0 + s * 8);
        }
        #pragma unroll
        for (int l = 0; l < 4; l++) {
            const int idx = tid + l * 128;
            const int arr = idx >> 8, rr = (idx >> 3) & 31, s = idx & 7;
            cp16(base + R_BOFF + arr * R_BARR + rr * 144 + s * 16,
                 (arr ? bL : bH) + (rowB + rr) * 512 + col0 + s * 8);
        }
        CPA_COMMIT();
    };

    load_chunk(0); load_chunk(1);
    for (int ch = 0; ch < 6; ch++) {
        if (ch + 2 < 6) load_chunk(ch + 2);
        if (ch < 4) asm volatile("cp.async.wait_group 2;" ::: "memory");
        else if (ch == 4) CPA_WAIT1();
        else CPA_WAIT0();
        __syncthreads();
        const uint32_t base = sb + (ch % 3) * R_BUF;
        #pragma unroll
        for (int ks = 0; ks < 2; ks++) {
            uint32_t ahf[2][4], alf[2][4], bb[2][4];
            #pragma unroll
            for (int mt = 0; mt < 2; mt++) {
                const uint32_t ra = base + (wm + mt * 16 + fRow) * 80 + (ks * 16 + fK) * 2;
                ldx4(ahf[mt], ra);
                ldx4(alf[mt], ra + R_AARR);
            }
            #pragma unroll
            for (int nt = 0; nt < 2; nt++) {
                const uint32_t rb = base + R_BOFF + (ks * 16 + tK) * 144 + (wn + nt * 16 + tN) * 2;
                ldx4t(bb[nt], rb);
            }
            #pragma unroll
            for (int mt = 0; mt < 2; mt++)
                #pragma unroll
                for (int nt = 0; nt < 2; nt++) {
                    mma16816(acc[mt][nt*2],   ahf[mt], bb[nt][0], bb[nt][1]);
                    mma16816(acc[mt][nt*2+1], ahf[mt], bb[nt][2], bb[nt][3]);
                    mma16816(acc[mt][nt*2],   alf[mt], bb[nt][0], bb[nt][1]);
                    mma16816(acc[mt][nt*2+1], alf[mt], bb[nt][2], bb[nt][3]);
                }
            #pragma unroll
            for (int nt = 0; nt < 2; nt++) {
                const uint32_t rb = base + R_BOFF + R_BARR + (ks * 16 + tK) * 144 + (wn + nt * 16 + tN) * 2;
                ldx4t(bb[nt], rb);
            }
            #pragma unroll
            for (int mt = 0; mt < 2; mt++)
                #pragma unroll
                for (int nt = 0; nt < 2; nt++) {
                    mma16816(acc[mt][nt*2],   ahf[mt], bb[nt][0], bb[nt][1]);
                    mma16816(acc[mt][nt*2+1], ahf[mt], bb[nt][2], bb[nt][3]);
                }
        }
        __syncthreads();
    }

    #pragma unroll
    for (int mt = 0; mt < 2; mt++)
        #pragma unroll
        for (int h = 0; h < 2; h++) {
            const int m = wm + mt * 16 + h * 8 + (lane >> 2);
            const int pos = (c & 15) * 64 + m;
            const float scale = rsqrtf((float)(pos + 1) * 64.0f);
            const long orow = ((long)c * 64 + m) * 512;
            #pragma unroll
            for (int n8 = 0; n8 < 4; n8++) {
                const int col = col0 + wn + n8 * 8 + (lane & 3) * 2;
                float2 o;
                o.x = acc[mt][n8][h*2+0] * scale;
                o.y = acc[mt][n8][h*2+1] * scale;
                *(float2*)&Out[orow + col] = o;
            }
        }
}

// ================= prep ====================================================
__global__ __launch_bounds__(256)
void prep_kernel(const float* __restrict__ x,
                 const float* __restrict__ W0, const float* __restrict__ W1,
                 const float* __restrict__ W2, const float* __restrict__ W3,
                 const float* __restrict__ Wk2, const float* __restrict__ Wq2,
                 bf16* __restrict__ xh, bf16* __restrict__ xl,
                 bf16* __restrict__ Wth, bf16* __restrict__ Wtl,
                 bf16* __restrict__ Wph, bf16* __restrict__ Wpl)
{
    const int bid = blockIdx.x, tid = threadIdx.x;
    if (bid < 1024) {
        const int i = bid * 256 + tid;
        float4 v = ((const float4*)x)[i];
        bsplit2(v.x, v.y, xh + i * 4,     xl + i * 4);
        bsplit2(v.z, v.w, xh + i * 4 + 2, xl + i * 4 + 2);
    } else if (bid < 2048) {
        const int widx = bid - 1024;
        const int z = widx >> 8, tile = widx & 255;
        const int k0 = (tile >> 4) * 32, n0 = (tile & 15) * 32;
        const float* W = z == 0 ? W0 : z == 1 ? W1 : z == 2 ? W2 : W3;
        __shared__ float t[32][33];
        #pragma unroll
        for (int j = 0; j < 4; j++) {
            const int r = (tid >> 5) + j * 8;
            t[r][tid & 31] = W[(long)(k0 + r) * 512 + n0 + (tid & 31)];
        }
        __syncthreads();
        #pragma unroll
        for (int j = 0; j < 4; j++) {
            const int nr = (tid >> 5) + j * 8, kc = tid & 31;
            const float v = t[kc][nr];
            const long o = (long)z * 262144 + (long)(n0 + nr) * 512 + k0 + kc;
            bf16 h = __float2bfloat16(v);
            Wth[o] = h;
            Wtl[o] = __float2bfloat16(v - __bfloat162float(h));
        }
    } else {
        const int widx = bid - 2048;
        const int z = widx >> 5, tile = widx & 31;
        const int k0 = (tile >> 1) * 32, n0 = (tile & 1) * 32;
        const float* W = z ? Wq2 : Wk2;
        __shared__ float t[32][33];
        #pragma unroll
        for (int j = 0; j < 4; j++) {
            const int r = (tid >> 5) + j * 8;
            t[r][tid & 31] = W[(long)(k0 + r) * 64 + n0 + (tid & 31)];
        }
        __syncthreads();
        #pragma unroll
        for (int j = 0; j < 4; j++) {
            const int nr = (tid >> 5) + j * 8, kc = tid & 31;
            const float v = t[kc][nr];
            const long o = (long)(z * 64 + n0 + nr) * 512 + k0 + kc;
            bf16 h = __float2bfloat16(v);
            Wph[o] = h;
            Wpl[o] = __float2bfloat16(v - __bfloat162float(h));
        }
    }
}

// ================= prefix ==================================================
__global__ __launch_bounds__(256)
void prefix_kernel(const float4* __restrict__ S, bf16* __restrict__ Ph,
                   bf16* __restrict__ Pl)
{
    int gidx = blockIdx.x * 256 + threadIdx.x;
    int b = gidx >> 14;
    int i = gidx & 16383;
    long base = (long)b * 16 * 16384 + i;
    float4 run = make_float4(0.f, 0.f, 0.f, 0.f);
    #pragma unroll
    for (int c = 0; c < 16; c++) {
        long idx = base + (long)c * 16384;
        long e = idx * 4;
        bsplit2(run.x, run.y, Ph + e,     Pl + e);
        bsplit2(run.z, run.w, Ph + e + 2, Pl + e + 2);
        float4 s = S[idx];
        run.x += s.x; run.y += s.y; run.z += s.z; run.w += s.w;
    }
}

// ================= LayerNorm (warp-per-row) ================================
__global__ __launch_bounds__(256)
void ln_kernel(const float* __restrict__ X, const float* __restrict__ gg,
               const float* __restrict__ bb, bf16* __restrict__ oh,
               bf16* __restrict__ ol)
{
    const int row = blockIdx.x * 8 + (threadIdx.x >> 5);
    const int lane = threadIdx.x & 31;
    const float4* Xr = (const float4*)(X + (long)row * 512);
    float4 v[4];
    float s = 0.f, sq = 0.f;
    #pragma unroll
    for (int q = 0; q < 4; q++) {
        v[q] = Xr[lane + 32 * q];
        s  += v[q].x + v[q].y + v[q].z + v[q].w;
        sq += v[q].x * v[q].x + v[q].y * v[q].y + v[q].z * v[q].z + v[q].w * v[q].w;
    }
    #pragma unroll
    for (int o = 16; o; o >>= 1) {
        s  += __shfl_xor_sync(0xFFFFFFFFu, s, o);
        sq += __shfl_xor_sync(0xFFFFFFFFu, sq, o);
    }
    const float mean = s * (1.0f / 512.0f);
    const float var  = sq * (1.0f / 512.0f) - mean * mean;
    const float rs   = rsqrtf(var + 1e-5f);
    #pragma unroll
    for (int q = 0; q < 4; q++) {
        const int idx = lane + 32 * q;
        float4 g4 = ((const float4*)gg)[idx];
        float4 b4 = ((const float4*)bb)[idx];
        float o0 = (v[q].x - mean) * rs * g4.x + b4.x;
        float o1 = (v[q].y - mean) * rs * g4.y + b4.y;
        float o2 = (v[q].z - mean) * rs * g4.z + b4.z;
        float o3 = (v[q].w - mean) * rs * g4.w + b4.w;
        long e = (long)row * 512 + idx * 4;
        bsplit2(o0, o1, oh + e,     ol + e);
        bsplit2(o2, o3, oh + e + 2, ol + e + 2);
    }
}

// ================= launch =================
extern "C" void kernel_launch(void* const* d_in, const int* in_sizes, int n_in,
                              void* d_out, int out_size)
{
    const float* x    = (const float*)d_in[0];
    const float* Wk1  = (const float*)d_in[1];
    const float* bk1  = (const float*)d_in[2];
    const float* Wk2  = (const float*)d_in[3];
    const float* bk2  = (const float*)d_in[4];
    const float* Wq1  = (const float*)d_in[5];
    const float* bq1  = (const float*)d_in[6];
    const float* Wq2  = (const float*)d_in[7];
    const float* bq2  = (const float*)d_in[8];
    const float* Wv   = (const float*)d_in[9];
    const float* bv   = (const float*)d_in[10];
    const float* ln_g = (const float*)d_in[11];
    const float* ln_b = (const float*)d_in[12];
    const float* Wo   = (const float*)d_in[13];
    const float* bo   = (const float*)d_in[14];
    float* out = (float*)d_out;

    void* p;
    cudaGetSymbolAddress(&p, g_xh);    bf16* xh    = (bf16*)p;
    cudaGetSymbolAddress(&p, g_xl);    bf16* xl    = (bf16*)p;
    cudaGetSymbolAddress(&p, g_Wth);   bf16* Wth   = (bf16*)p;
    cudaGetSymbolAddress(&p, g_Wtl);   bf16* Wtl   = (bf16*)p;
    cudaGetSymbolAddress(&p, g_Wph);   bf16* Wph   = (bf16*)p;
    cudaGetSymbolAddress(&p, g_Wpl);   bf16* Wpl   = (bf16*)p;
    cudaGetSymbolAddress(&p, g_Hkh);   bf16* Hkh   = (bf16*)p;
    cudaGetSymbolAddress(&p, g_Hkl);   bf16* Hkl   = (bf16*)p;
    cudaGetSymbolAddress(&p, g_Hqh);   bf16* Hqh   = (bf16*)p;
    cudaGetSymbolAddress(&p, g_Hql);   bf16* Hql   = (bf16*)p;
    cudaGetSymbolAddress(&p, g_Vh);    bf16* Vh    = (bf16*)p;
    cudaGetSymbolAddress(&p, g_Vl);    bf16* Vl    = (bf16*)p;
    cudaGetSymbolAddress(&p, g_CSkh);  bf16* CSkh  = (bf16*)p;
    cudaGetSymbolAddress(&p, g_CSkl);  bf16* CSkl  = (bf16*)p;
    cudaGetSymbolAddress(&p, g_CSqh);  bf16* CSqh  = (bf16*)p;
    cudaGetSymbolAddress(&p, g_CSql);  bf16* CSql  = (bf16*)p;
    cudaGetSymbolAddress(&p, g_CSkTh); bf16* CSkTh = (bf16*)p;
    cudaGetSymbolAddress(&p, g_CSkTl); bf16* CSkTl = (bf16*)p;
    cudaGetSymbolAddress(&p, g_Ach);   bf16* Ach   = (bf16*)p;
    cudaGetSymbolAddress(&p, g_Acl);   bf16* Acl   = (bf16*)p;
    cudaGetSymbolAddress(&p, g_S);     float* S    = (float*)p;
    cudaGetSymbolAddress(&p, g_Ph);    bf16* Ph    = (bf16*)p;
    cudaGetSymbolAddress(&p, g_Pl);    bf16* Pl    = (bf16*)p;
    cudaGetSymbolAddress(&p, g_R);     float* R    = (float*)p;
    cudaGetSymbolAddress(&p, g_LNh);   bf16* LNh   = (bf16*)p;
    cudaGetSymbolAddress(&p, g_LNl);   bf16* LNl   = (bf16*)p;

    static int attr_set = 0;
    if (!attr_set) {
        cudaFuncSetAttribute(mma_gemm<0>, cudaFuncAttributeMaxDynamicSharedMemorySize, X_SMEM);
        cudaFuncSetAttribute(mma_gemm<1>, cudaFuncAttributeMaxDynamicSharedMemorySize, X_SMEM);
        cudaFuncSetAttribute(phase_mma,   cudaFuncAttributeMaxDynamicSharedMemorySize, P_SMEM);
        cudaFuncSetAttribute(sac_mma,     cudaFuncAttributeMaxDynamicSharedMemorySize, SAC_SMEM);
        cudaFuncSetAttribute(r_mma,       cudaFuncAttributeMaxDynamicSharedMemorySize, R_SMEM);
        attr_set = 1;
    }

    // 0) conversions
    prep_kernel<<<2112, 256>>>(x, Wk1, Wq1, Wv, Wo, Wk2, Wq2,
                               xh, xl, Wth, Wtl, Wph, Wpl);

    // 1) XW: Hk(gelu), Hq(gelu), V(bias). grid (8,32,3)=768, 4-5 CTAs/SM.
    mma_gemm<0><<<dim3(8,32,3), 128, X_SMEM>>>(
        xh, xl, Wth, Wtl, bk1, bq1, bv, nullptr,
        Hkh, Hkl, Hqh, Hql, Vh, Vl, nullptr);

    // 2) Phases (split-K, 256 thr). grid (1,64,2)=128.
    phase_mma<<<dim3(1,64,2), 256, P_SMEM>>>(
        Hkh, Hkl, Hqh, Hql, Wph, Wpl, bk2, bq2,
        CSkh, CSkl, CSqh, CSql, CSkTh, CSkTl);

    // 3) S + Ac. grid (9,1,32)=288.
    sac_mma<<<dim3(9,1,32), 256, SAC_SMEM>>>(
        CSkTh, CSkTl, Vh, Vl, CSqh, CSql, CSkh, CSkl, S, Ach, Acl);

    // 4) exclusive prefix -> split bf16 P
    prefix_kernel<<<128, 256>>>((const float4*)S, Ph, Pl);

    // 5) R. grid (8,1,32)=256.
    r_mma<<<dim3(8,1,32), 128, R_SMEM>>>(
        CSqh, CSql, Ach, Acl, Ph, Pl, Vh, Vl, R);

    // 6) LN -> split bf16 (warp-per-row)
    ln_kernel<<<256, 256>>>(R, ln_g, ln_b, LNh, LNl);

    // 7) out = x + LN @ Wo + bo. grid (8,32)=256.
    mma_gemm<1><<<dim3(8,32,1), 128, X_SMEM>>>(
        LNh, LNl, Wth + 3L*262144, Wtl + 3L*262144, bo, nullptr, nullptr, x,
        nullptr, nullptr, nullptr, nullptr, nullptr, nullptr, out);
}

// round 14
// speedup vs baseline: 1.0049x; 1.0049x over previous
#include <cuda_runtime.h>
#include <cuda_bf16.h>
#include <math.h>
#include <stdint.h>

#define PI_F 3.14159265358979323846f
typedef __nv_bfloat16 bf16;

// ---------------- scratch ----------------
__device__ bf16 g_xh  [2048 * 512];
__device__ bf16 g_xl  [2048 * 512];
__device__ bf16 g_Wth [4 * 512 * 512];
__device__ bf16 g_Wtl [4 * 512 * 512];
__device__ bf16 g_Wph [128 * 512];
__device__ bf16 g_Wpl [128 * 512];
__device__ bf16 g_Hkh [2048 * 512];
__device__ bf16 g_Hkl [2048 * 512];
__device__ bf16 g_Hqh [2048 * 512];
__device__ bf16 g_Hql [2048 * 512];
__device__ bf16 g_Vh  [2048 * 512];
__device__ bf16 g_Vl  [2048 * 512];
__device__ bf16 g_CSkh[2048 * 128];
__device__ bf16 g_CSkl[2048 * 128];
__device__ bf16 g_CSqh[2048 * 128];
__device__ bf16 g_CSql[2048 * 128];
__device__ bf16 g_CSkTh[32 * 128 * 64];
__device__ bf16 g_CSkTl[32 * 128 * 64];
__device__ bf16 g_Ach [32 * 64 * 64];
__device__ bf16 g_Acl [32 * 64 * 64];
__device__ float g_S  [32 * 128 * 512];
__device__ bf16 g_Ph  [32 * 128 * 512];
__device__ bf16 g_Pl  [32 * 128 * 512];
__device__ float g_R  [2048 * 512];
__device__ bf16 g_LNh [2048 * 512];
__device__ bf16 g_LNl [2048 * 512];

// ================= PTX helpers =================
__device__ __forceinline__ uint32_t smem_u32(const void* p) {
    uint32_t a;
    asm("{ .reg .u64 t; cvta.to.shared.u64 t, %1; cvt.u32.u64 %0, t; }" : "=r"(a) : "l"(p));
    return a;
}
__device__ __forceinline__ void cp16(uint32_t dst, const void* src) {
    asm volatile("cp.async.cg.shared.global [%0], [%1], 16;" :: "r"(dst), "l"(src));
}
__device__ __forceinline__ void ldx4(uint32_t* r, uint32_t addr) {
    asm volatile("ldmatrix.sync.aligned.m8n8.x4.shared.b16 {%0,%1,%2,%3}, [%4];"
        : "=r"(r[0]), "=r"(r[1]), "=r"(r[2]), "=r"(r[3]) : "r"(addr));
}
__device__ __forceinline__ void ldx4t(uint32_t* r, uint32_t addr) {
    asm volatile("ldmatrix.sync.aligned.m8n8.x4.trans.shared.b16 {%0,%1,%2,%3}, [%4];"
        : "=r"(r[0]), "=r"(r[1]), "=r"(r[2]), "=r"(r[3]) : "r"(addr));
}
__device__ __forceinline__ void mma16816(float* c, const uint32_t* a,
                                         uint32_t b0, uint32_t b1) {
    asm volatile("mma.sync.aligned.m16n8k16.row.col.f32.bf16.bf16.f32 "
        "{%0,%1,%2,%3}, {%4,%5,%6,%7}, {%8,%9}, {%0,%1,%2,%3};"
        : "+f"(c[0]), "+f"(c[1]), "+f"(c[2]), "+f"(c[3])
        : "r"(a[0]), "r"(a[1]), "r"(a[2]), "r"(a[3]), "r"(b0), "r"(b1));
}
__device__ __forceinline__ void bsplit2(float v0, float v1, bf16* hd, bf16* ld) {
    __nv_bfloat162 h, l;
    h.x = __float2bfloat16(v0); h.y = __float2bfloat16(v1);
    l.x = __float2bfloat16(v0 - __bfloat162float(h.x));
    l.y = __float2bfloat16(v1 - __bfloat162float(h.y));
    *(__nv_bfloat162*)hd = h; *(__nv_bfloat162*)ld = l;
}
#define CPA_COMMIT() asm volatile("cp.async.commit_group;" ::: "memory")
#define CPA_WAIT1()  asm volatile("cp.async.wait_group 1;" ::: "memory")
#define CPA_WAIT0()  asm volatile("cp.async.wait_group 0;" ::: "memory")

// ================= XW / OUT GEMM: 64xBN tile, 128 thr, 4 warps (2m x 2n) ====
static constexpr int XA_ARR = 64 * 80;
static constexpr int XB_OFF = 2 * XA_ARR;
static constexpr int X0_SMEM = 2 * (XB_OFF + 2 * 128 * 80);  // 61440
static constexpr int X1_SMEM = 2 * (XB_OFF + 2 * 64 * 80);   // 40960

template<int MODE>   // 0: BN=128 XW (split bf16 out, gelu z<2); 1: BN=64 fp32+resid
__global__ __launch_bounds__(128, 3)
void mma_gemm(const bf16* __restrict__ Ah, const bf16* __restrict__ Al,
              const bf16* __restrict__ Wth, const bf16* __restrict__ Wtl,
              const float* __restrict__ b0, const float* __restrict__ b1,
              const float* __restrict__ b2, const float* __restrict__ resid,
              bf16* __restrict__ O0h, bf16* __restrict__ O0l,
              bf16* __restrict__ O1h, bf16* __restrict__ O1l,
              bf16* __restrict__ O2h, bf16* __restrict__ O2l,
              float* __restrict__ Cout)
{
    constexpr int BN = (MODE == 0) ? 128 : 64;
    constexpr int NT = BN / 32;
    constexpr int XB_ARR = BN * 80;
    constexpr int X_BUF  = XB_OFF + 2 * XB_ARR;
    constexpr int BLD = BN / 16;

    extern __shared__ __align__(128) char smem[];
    const uint32_t sb = smem_u32(smem);
    const int tid = threadIdx.x, wid = tid >> 5, lane = tid & 31;
    const int row0 = blockIdx.y * 64, col0 = blockIdx.x * BN;
    const int z = (MODE == 0) ? (int)blockIdx.z : 0;
    const bf16* Bh = Wth + (long)z * 262144;
    const bf16* Bl = Wtl + (long)z * 262144;
    const float* bias = (z == 0) ? b0 : (z == 1 ? b1 : b2);
    const bool gelu = (MODE == 0) && (z < 2);
    bf16* Oh = (z == 0) ? O0h : (z == 1 ? O1h : O2h);
    bf16* Ol = (z == 0) ? O0l : (z == 1 ? O1l : O2l);

    const int wm = (wid & 1) * 32, wn = (wid >> 1) * (BN / 2);
    float acc[2][2 * NT][4];
    #pragma unroll
    for (int i = 0; i < 2; i++)
        #pragma unroll
        for (int j = 0; j < 2 * NT; j++)
            #pragma unroll
            for (int e = 0; e < 4; e++) acc[i][j][e] = 0.0f;

    const int g = lane >> 3, wr = lane & 7;
    const int fRow = wr + (g & 1) * 8, fK = (g >> 1) * 8;

    auto load_chunk = [&](int ch, int b) {
        const int k0 = ch * 32;
        const uint32_t base = sb + b * X_BUF;
        #pragma unroll
        for (int l = 0; l < 4; l++) {
            const int idx = tid + l * 128;
            const int arr = idx >> 8, rr = (idx >> 2) & 63, s = idx & 3;
            cp16(base + arr * XA_ARR + rr * 80 + s * 16,
                 (arr ? Al : Ah) + (long)(row0 + rr) * 512 + k0 + s * 8);
        }
        #pragma unroll
        for (int l = 0; l < BLD; l++) {
            const int idx = tid + l * 128;
            const int arr = idx / (BN * 4), rr = (idx >> 2) % BN, s = idx & 3;
            cp16(base + XB_OFF + arr * XB_ARR + rr * 80 + s * 16,
                 (arr ? Bl : Bh) + (long)(col0 + rr) * 512 + k0 + s * 8);
        }
        CPA_COMMIT();
    };

    load_chunk(0, 0);
    for (int ch = 0; ch < 16; ch++) {
        const int b = ch & 1;
        if (ch < 15) { load_chunk(ch + 1, b ^ 1); CPA_WAIT1(); }
        else CPA_WAIT0();
        __syncthreads();
        const uint32_t base = sb + b * X_BUF;
        #pragma unroll
        for (int ks = 0; ks < 2; ks++) {
            uint32_t ahf[2][4], alf[2][4], bb[NT][4];
            #pragma unroll
            for (int mt = 0; mt < 2; mt++) {
                const uint32_t ra = base + (wm + mt * 16 + fRow) * 80 + (ks * 16 + fK) * 2;
                ldx4(ahf[mt], ra);
                ldx4(alf[mt], ra + XA_ARR);
            }
            #pragma unroll
            for (int nt = 0; nt < NT; nt++) {
                const uint32_t rb = base + XB_OFF + (wn + nt * 16 + fRow) * 80 + (ks * 16 + fK) * 2;
                ldx4(bb[nt], rb);
            }
            #pragma unroll
            for (int mt = 0; mt < 2; mt++)
                #pragma unroll
                for (int nt = 0; nt < NT; nt++) {
                    mma16816(acc[mt][nt*2],   ahf[mt], bb[nt][0], bb[nt][2]);
                    mma16816(acc[mt][nt*2+1], ahf[mt], bb[nt][1], bb[nt][3]);
                    mma16816(acc[mt][nt*2],   alf[mt], bb[nt][0], bb[nt][2]);
                    mma16816(acc[mt][nt*2+1], alf[mt], bb[nt][1], bb[nt][3]);
                }
            #pragma unroll
            for (int nt = 0; nt < NT; nt++) {
                const uint32_t rb = base + XB_OFF + XB_ARR + (wn + nt * 16 + fRow) * 80 + (ks * 16 + fK) * 2;
                ldx4(bb[nt], rb);
            }
            #pragma unroll
            for (int mt = 0; mt < 2; mt++)
                #pragma unroll
                for (int nt = 0; nt < NT; nt++) {
                    mma16816(acc[mt][nt*2],   ahf[mt], bb[nt][0], bb[nt][2]);
                    mma16816(acc[mt][nt*2+1], ahf[mt], bb[nt][1], bb[nt][3]);
                }
        }
        __syncthreads();
    }

    #pragma unroll
    for (int mt = 0; mt < 2; mt++)
        #pragma unroll
        for (int h = 0; h < 2; h++) {
            const int row = row0 + wm + mt * 16 + h * 8 + (lane >> 2);
            #pragma unroll
            for (int n8 = 0; n8 < 2 * NT; n8++) {
                const int col = col0 + wn + n8 * 8 + (lane & 3) * 2;
                float v0 = acc[mt][n8][h * 2 + 0];
                float v1 = acc[mt][n8][h * 2 + 1];
                const float2 bq = *(const float2*)&bias[col];
                v0 += bq.x; v1 += bq.y;
                if (MODE == 0) {
                    if (gelu) {
                        v0 = 0.5f * v0 * (1.0f + erff(v0 * 0.70710678118654752f));
                        v1 = 0.5f * v1 * (1.0f + erff(v1 * 0.70710678118654752f));
                    }
                    bsplit2(v0, v1, Oh + (long)row * 512 + col, Ol + (long)row * 512 + col);
                } else {
                    const float2 r2 = *(const float2*)&resid[(long)row * 512 + col];
                    float2 o; o.x = v0 + r2.x; o.y = v1 + r2.y;
                    *(float2*)&Cout[(long)row * 512 + col] = o;
                }
            }
        }
}

// ================= phase GEMM: 16x64 tile, 256 thr, split-K (2 groups) =====
// Warps 0-3: K[0:256] (one 16-col slice each); warps 4-7: K[256:512].
static constexpr int PH_A    = 16 * 80;                 // 1280 per array
static constexpr int PH_BOFF = 2 * PH_A;                // 2560
static constexpr int PH_HALF = PH_BOFF + 2 * 64 * 80;   // 12800
static constexpr int PH_STG  = 2 * PH_HALF;             // 25600
static constexpr int P_SMEM  = 2 * PH_STG;              // 51200

__global__ __launch_bounds__(256)
void phase_mma(const bf16* __restrict__ Hkh, const bf16* __restrict__ Hkl,
               const bf16* __restrict__ Hqh, const bf16* __restrict__ Hql,
               const bf16* __restrict__ Wph, const bf16* __restrict__ Wpl,
               const float* __restrict__ bk2, const float* __restrict__ bq2,
               bf16* __restrict__ CSkh, bf16* __restrict__ CSkl,
               bf16* __restrict__ CSqh, bf16* __restrict__ CSql,
               bf16* __restrict__ CSkTh, bf16* __restrict__ CSkTl)
{
    extern __shared__ __align__(128) char smem[];
    const uint32_t sb = smem_u32(smem);
    const int tid = threadIdx.x, wid = tid >> 5, lane = tid & 31;
    const int z = blockIdx.z, row0 = blockIdx.y * 16;
    const bf16* Ah = z ? Hqh : Hkh;
    const bf16* Al = z ? Hql : Hkl;
    const bf16* Bh = Wph + (long)z * 64 * 512;
    const bf16* Bl = Wpl + (long)z * 64 * 512;
    const float* bias = z ? bq2 : bk2;

    const int grp = wid >> 2;         // K half
    const int wn = (wid & 3) * 16;    // 16-col slice per warp
    float acc[2][4];
    #pragma unroll
    for (int j = 0; j < 2; j++)
        #pragma unroll
        for (int e = 0; e < 4; e++) acc[j][e] = 0.0f;

    const int g = lane >> 3, wr = lane & 7;
    const int fRow = wr + (g & 1) * 8, fK = (g >> 1) * 8;

    auto load_chunk = [&](int ch) {
        const int k0 = ch * 32;
        const uint32_t base = sb + (ch & 1) * PH_STG;
        {   // A: 2 halves x 2 arrays x 16 rows x 4 sixteens = 256 cp16
            const int idx = tid;
            const int hf = idx >> 7, ii = idx & 127;
            const int arr = ii >> 6, pos = ii & 63, rr = pos >> 2, s = pos & 3;
            cp16(base + hf * PH_HALF + arr * PH_A + rr * 80 + s * 16,
                 (arr ? Al : Ah) + (long)(row0 + rr) * 512 + hf * 256 + k0 + s * 8);
        }
        #pragma unroll
        for (int l = 0; l < 4; l++) {   // B: 2 halves x 2 arrays x 64 rows x 4 = 1024
            const int idx = tid + l * 256;
            const int hf = idx >> 9, ii = idx & 511;
            const int arr = ii >> 8, pos = ii & 255, rr = pos >> 2, s = pos & 3;
            cp16(base + hf * PH_HALF + PH_BOFF + arr * 5120 + rr * 80 + s * 16,
                 (arr ? Bl : Bh) + (long)rr * 512 + hf * 256 + k0 + s * 8);
        }
        CPA_COMMIT();
    };

    load_chunk(0);
    for (int ch = 0; ch < 8; ch++) {
        if (ch < 7) { load_chunk(ch + 1); CPA_WAIT1(); }
        else CPA_WAIT0();
        __syncthreads();
        const uint32_t hbase = sb + (ch & 1) * PH_STG + grp * PH_HALF;
        #pragma unroll
        for (int ks = 0; ks < 2; ks++) {
            uint32_t ahf[4], alf[4], bb[4];
            {
                const uint32_t ra = hbase + fRow * 80 + (ks * 16 + fK) * 2;
                ldx4(ahf, ra);
                ldx4(alf, ra + PH_A);
            }
            const uint32_t rb = hbase + PH_BOFF + (wn + fRow) * 80 + (ks * 16 + fK) * 2;
            ldx4(bb, rb);
            mma16816(acc[0], ahf, bb[0], bb[2]);
            mma16816(acc[1], ahf, bb[1], bb[3]);
            mma16816(acc[0], alf, bb[0], bb[2]);
            mma16816(acc[1], alf, bb[1], bb[3]);
            ldx4(bb, rb + 5120);
            mma16816(acc[0], ahf, bb[0], bb[2]);
            mma16816(acc[1], ahf, bb[1], bb[3]);
        }
        __syncthreads();
    }

    // split-K reduction via smem
    float* red = (float*)smem;
    if (grp == 1) {
        #pragma unroll
        for (int j = 0; j < 2; j++)
            *(float4*)&red[(tid - 128) * 8 + j * 4] = *(float4*)acc[j];
    }
    __syncthreads();
    if (tid < 128) {
        #pragma unroll
        for (int j = 0; j < 2; j++) {
            float4 o = *(float4*)&red[tid * 8 + j * 4];
            acc[j][0] += o.x; acc[j][1] += o.y; acc[j][2] += o.z; acc[j][3] += o.w;
        }
        #pragma unroll
        for (int h = 0; h < 2; h++) {
            const int row = row0 + h * 8 + (lane >> 2);
            #pragma unroll
            for (int n8 = 0; n8 < 2; n8++) {
                const int n = wn + n8 * 8 + (lane & 3) * 2;
                float v0 = acc[n8][h * 2 + 0] + bias[n];
                float v1 = acc[n8][h * 2 + 1] + bias[n + 1];
                float p0 = tanhf(v0) * PI_F, p1 = tanhf(v1) * PI_F;
                float c0, s0, c1, s1;
                sincosf(p0, &s0, &c0);
                sincosf(p1, &s1, &c1);
                bf16* Rh = z ? CSqh : CSkh;
                bf16* Rl = z ? CSql : CSkl;
                const long rb_ = (long)row * 128;
                bsplit2(c0, c1, Rh + rb_ + n,      Rl + rb_ + n);
                bsplit2(s0, s1, Rh + rb_ + n + 64, Rl + rb_ + n + 64);
                if (!z) {
                    const int c = row >> 6, ro = row & 63;
                    const long t0 = (long)c * 8192 + (long)n * 64 + ro;
                    bf16 h0 = __float2bfloat16(c0);
                    bf16 h1 = __float2bfloat16(c1);
                    bf16 h2 = __float2bfloat16(s0);
                    bf16 h3 = __float2bfloat16(s1);
                    CSkTh[t0]        = h0;
                    CSkTh[t0 + 64]   = h1;
                    CSkTh[t0 + 4096] = h2;
                    CSkTh[t0 + 4160] = h3;
                    CSkTl[t0]        = __float2bfloat16(c0 - __bfloat162float(h0));
                    CSkTl[t0 + 64]   = __float2bfloat16(c1 - __bfloat162float(h1));
                    CSkTl[t0 + 4096] = __float2bfloat16(s0 - __bfloat162float(h2));
                    CSkTl[t0 + 4160] = __float2bfloat16(s1 - __bfloat162float(h3));
                }
            }
        }
    }
}

// ================= S + Ac combined launch ==================================
static constexpr int S_AARR = 128 * 80;
static constexpr int S_BOFF = 2 * S_AARR;
static constexpr int S_BARR = 32 * 144;
static constexpr int S_BUF  = S_BOFF + 2 * S_BARR;
static constexpr int SAC_SMEM = 2 * S_BUF;
static constexpr int AC_AARR = 64 * 80;
static constexpr int AC_BOFF = 2 * AC_AARR;
static constexpr int AC_BUF  = 2 * AC_BOFF;

__global__ __launch_bounds__(256)
void sac_mma(const bf16* __restrict__ CSkTh, const bf16* __restrict__ CSkTl,
             const bf16* __restrict__ Vh, const bf16* __restrict__ Vl,
             const bf16* __restrict__ CSqh, const bf16* __restrict__ CSql,
             const bf16* __restrict__ CSkh, const bf16* __restrict__ CSkl,
             float* __restrict__ S, bf16* __restrict__ Ach, bf16* __restrict__ Acl)
{
    extern __shared__ __align__(128) char smem[];
    const uint32_t sb = smem_u32(smem);
    const int tid = threadIdx.x, wid = tid >> 5, lane = tid & 31;
    const int c = blockIdx.z;
    const int g = lane >> 3, wr = lane & 7;
    const int fRow = wr + (g & 1) * 8, fK = (g >> 1) * 8;
    const int tK = fRow, tN = (g >> 1) * 8;

    if (blockIdx.x < 8) {
        const int col0 = blockIdx.x * 64;
        const int wm = (wid & 3) * 32, wn = (wid >> 2) * 32;
        float acc[2][4][4];
        #pragma unroll
        for (int i = 0; i < 2; i++)
            #pragma unroll
            for (int j = 0; j < 4; j++)
                #pragma unroll
                for (int e = 0; e < 4; e++) acc[i][j][e] = 0.0f;

        auto load_chunk = [&](int ch, int b) {
            const int k0 = ch * 32;
            const uint32_t base = sb + b * S_BUF;
            #pragma unroll
            for (int l = 0; l < 4; l++) {
                const int idx = tid + l * 256;
                const int arr = idx >> 9, rr = (idx >> 2) & 127, s = idx & 3;
                cp16(base + arr * S_AARR + rr * 80 + s * 16,
                     (arr ? CSkTl : CSkTh) + (long)c * 8192 + (long)rr * 64 + k0 + s * 8);
            }
            #pragma unroll
            for (int l = 0; l < 2; l++) {
                const int idx = tid + l * 256;
                const int arr = idx >> 8, rr = (idx >> 3) & 31, s = idx & 7;
                cp16(base + S_BOFF + arr * S_BARR + rr * 144 + s * 16,
                     (arr ? Vl : Vh) + ((long)c * 64 + k0 + rr) * 512 + col0 + s * 8);
            }
            CPA_COMMIT();
        };

        load_chunk(0, 0);
        load_chunk(1, 1);
        for (int ch = 0; ch < 2; ch++) {
            if (ch == 0) CPA_WAIT1(); else CPA_WAIT0();
            __syncthreads();
            const uint32_t base = sb + ch * S_BUF;
            #pragma unroll
            for (int ks = 0; ks < 2; ks++) {
                uint32_t ahf[2][4], alf[2][4], bb[2][4];
                #pragma unroll
                for (int mt = 0; mt < 2; mt++) {
                    const uint32_t ra = base + (wm + mt * 16 + fRow) * 80 + (ks * 16 + fK) * 2;
                    ldx4(ahf[mt], ra);
                    ldx4(alf[mt], ra + S_AARR);
                }
                #pragma unroll
                for (int nt = 0; nt < 2; nt++) {
                    const uint32_t rb = base + S_BOFF + (ks * 16 + tK) * 144 + (wn + nt * 16 + tN) * 2;
                    ldx4t(bb[nt], rb);
                }
                #pragma unroll
                for (int mt = 0; mt < 2; mt++)
                    #pragma unroll
                    for (int nt = 0; nt < 2; nt++) {
                        mma16816(acc[mt][nt*2],   ahf[mt], bb[nt][0], bb[nt][1]);
                        mma16816(acc[mt][nt*2+1], ahf[mt], bb[nt][2], bb[nt][3]);
                        mma16816(acc[mt][nt*2],   alf[mt], bb[nt][0], bb[nt][1]);
                        mma16816(acc[mt][nt*2+1], alf[mt], bb[nt][2], bb[nt][3]);
                    }
                #pragma unroll
                for (int nt = 0; nt < 2; nt++) {
                    const uint32_t rb = base + S_BOFF + S_BARR + (ks * 16 + tK) * 144 + (wn + nt * 16 + tN) * 2;
                    ldx4t(bb[nt], rb);
                }
                #pragma unroll
                for (int mt = 0; mt < 2; mt++)
                    #pragma unroll
                    for (int nt = 0; nt < 2; nt++) {
                        mma16816(acc[mt][nt*2],   ahf[mt], bb[nt][0], bb[nt][1]);
                        mma16816(acc[mt][nt*2+1], ahf[mt], bb[nt][2], bb[nt][3]);
                    }
            }
            __syncthreads();
        }

        #pragma unroll
        for (int mt = 0; mt < 2; mt++)
            #pragma unroll
            for (int h = 0; h < 2; h++) {
                const int m = wm + mt * 16 + h * 8 + (lane >> 2);
                const long orow = (long)c * 65536 + (long)m * 512;
                #pragma unroll
                for (int n8 = 0; n8 < 4; n8++) {
                    const int col = col0 + wn + n8 * 8 + (lane & 3) * 2;
                    float2 o; o.x = acc[mt][n8][h*2+0]; o.y = acc[mt][n8][h*2+1];
                    *(float2*)&S[orow + col] = o;
                }
            }
    } else {
        const int wm = (wid & 1) * 32, wn = (wid >> 1) * 16;
        float acc[2][2][4];
        #pragma unroll
        for (int i = 0; i < 2; i++)
            #pragma unroll
            for (int j = 0; j < 2; j++)
                #pragma unroll
                for (int e = 0; e < 4; e++) acc[i][j][e] = 0.0f;

        auto load_chunk = [&](int ch, int b) {
            const int k0 = ch * 32;
            const uint32_t base = sb + b * AC_BUF;
            #pragma unroll
            for (int l = 0; l < 2; l++) {
                const int idx = tid + l * 256;
                const int arr = idx >> 8, rr = (idx >> 2) & 63, s = idx & 3;
                cp16(base + arr * AC_AARR + rr * 80 + s * 16,
                     (arr ? CSql : CSqh) + ((long)c * 64 + rr) * 128 + k0 + s * 8);
            }
            #pragma unroll
            for (int l = 0; l < 2; l++) {
                const int idx = tid + l * 256;
                const int arr = idx >> 8, rr = (idx >> 2) & 63, s = idx & 3;
                cp16(base + AC_BOFF + arr * AC_AARR + rr * 80 + s * 16,
                     (arr ? CSkl : CSkh) + ((long)c * 64 + rr) * 128 + k0 + s * 8);
            }
            CPA_COMMIT();
        };

        load_chunk(0, 0);
        for (int ch = 0; ch < 4; ch++) {
            const int b = ch & 1;
            if (ch < 3) { load_chunk(ch + 1, b ^ 1); CPA_WAIT1(); }
            else CPA_WAIT0();
            __syncthreads();
            const uint32_t base = sb + b * AC_BUF;
            #pragma unroll
            for (int ks = 0; ks < 2; ks++) {
                uint32_t ahf[2][4], alf[2][4], bb[4];
                #pragma unroll
                for (int mt = 0; mt < 2; mt++) {
                    const uint32_t ra = base + (wm + mt * 16 + fRow) * 80 + (ks * 16 + fK) * 2;
                    ldx4(ahf[mt], ra);
                    ldx4(alf[mt], ra + AC_AARR);
                }
                {
                    const uint32_t rb = base + AC_BOFF + (wn + fRow) * 80 + (ks * 16 + fK) * 2;
                    ldx4(bb, rb);
                }
                #pragma unroll
                for (int mt = 0; mt < 2; mt++) {
                    mma16816(acc[mt][0], ahf[mt], bb[0], bb[2]);
                    mma16816(acc[mt][1], ahf[mt], bb[1], bb[3]);
                    mma16816(acc[mt][0], alf[mt], bb[0], bb[2]);
                    mma16816(acc[mt][1], alf[mt], bb[1], bb[3]);
                }
                {
                    const uint32_t rb = base + AC_BOFF + AC_AARR + (wn + fRow) * 80 + (ks * 16 + fK) * 2;
                    ldx4(bb, rb);
                }
                #pragma unroll
                for (int mt = 0; mt < 2; mt++) {
                    mma16816(acc[mt][0], ahf[mt], bb[0], bb[2]);
                    mma16816(acc[mt][1], ahf[mt], bb[1], bb[3]);
                }
            }
            __syncthreads();
        }

        #pragma unroll
        for (int mt = 0; mt < 2; mt++)
            #pragma unroll
            for (int h = 0; h < 2; h++) {
                const int row = wm + mt * 16 + h * 8 + (lane >> 2);
                #pragma unroll
                for (int n8 = 0; n8 < 2; n8++) {
                    const int col = wn + n8 * 8 + (lane & 3) * 2;
                    float v0 = (col     <= row) ? acc[mt][n8][h*2+0] : 0.0f;
                    float v1 = (col + 1 <= row) ? acc[mt][n8][h*2+1] : 0.0f;
                    const long o = (long)c * 4096 + (long)row * 64 + col;
                    bsplit2(v0, v1, Ach + o, Acl + o);
                }
            }
    }
}

// ================= R GEMM: M64,N64,K192, 128 thr ===========================
static constexpr int R_AARR = 64 * 80;
static constexpr int R_BOFF = 2 * R_AARR;
static constexpr int R_BARR = 32 * 144;
static constexpr int R_BUF  = R_BOFF + 2 * R_BARR;
static constexpr int R_SMEM = 3 * R_BUF;

__global__ __launch_bounds__(128)
void r_mma(const bf16* __restrict__ CSqh, const bf16* __restrict__ CSql,
           const bf16* __restrict__ Ach, const bf16* __restrict__ Acl,
           const bf16* __restrict__ Ph, const bf16* __restrict__ Pl,
           const bf16* __restrict__ Vh, const bf16* __restrict__ Vl,
           float* __restrict__ Out)
{
    extern __shared__ __align__(128) char smem[];
    const uint32_t sb = smem_u32(smem);
    const int tid = threadIdx.x, wid = tid >> 5, lane = tid & 31;
    const int c = blockIdx.z, col0 = blockIdx.x * 64;
    const int wm = (wid & 1) * 32, wn = (wid >> 1) * 32;
    const int g = lane >> 3, wr = lane & 7;
    const int fRow = wr + (g & 1) * 8, fK = (g >> 1) * 8;
    const int tK = fRow, tN = (g >> 1) * 8;

    float acc[2][4][4];
    #pragma unroll
    for (int i = 0; i < 2; i++)
        #pragma unroll
        for (int j = 0; j < 4; j++)
            #pragma unroll
            for (int e = 0; e < 4; e++) acc[i][j][e] = 0.0f;

    auto load_chunk = [&](int ch) {
        const uint32_t base = sb + (ch % 3) * R_BUF;
        const bf16 *aH, *aL, *bH, *bL;
        int ldA, k0;
        long rowB;
        if (ch < 4) {
            aH = CSqh + (long)c * 8192; aL = CSql + (long)c * 8192;
            ldA = 128; k0 = ch * 32;
            bH = Ph; bL = Pl; rowB = (long)c * 128 + ch * 32;
        } else {
            aH = Ach + (long)c * 4096; aL = Acl + (long)c * 4096;
            ldA = 64; k0 = (ch - 4) * 32;
            bH = Vh; bL = Vl; rowB = (long)c * 64 + (ch - 4) * 32;
        }
        #pragma unroll
        for (int l = 0; l < 4; l++) {
            const int idx = tid + l * 128;
            const int arr = idx >> 8, rr = (idx >> 2) & 63, s = idx & 3;
            cp16(base + arr * R_AARR + rr * 80 + s * 16,
                 (arr ? aL : aH) + (long)rr * ldA + k0 + s * 8);
        }
        #pragma unroll
        for (int l = 0; l < 4; l++) {
            const int idx = tid + l * 128;
            const int arr = idx >> 8, rr = (idx >> 3) & 31, s = idx & 7;
            cp16(base + R_BOFF + arr * R_BARR + rr * 144 + s * 16,
                 (arr ? bL : bH) + (rowB + rr) * 512 + col0 + s * 8);
        }
        CPA_COMMIT();
    };

    load_chunk(0); load_chunk(1);
    for (int ch = 0; ch < 6; ch++) {
        if (ch + 2 < 6) load_chunk(ch + 2);
        if (ch < 4) asm volatile("cp.async.wait_group 2;" ::: "memory");
        else if (ch == 4) CPA_WAIT1();
        else CPA_WAIT0();
        __syncthreads();
        const uint32_t base = sb + (ch % 3) * R_BUF;
        #pragma unroll
        for (int ks = 0; ks < 2; ks++) {
            uint32_t ahf[2][4], alf[2][4], bb[2][4];
            #pragma unroll
            for (int mt = 0; mt < 2; mt++) {
                const uint32_t ra = base + (wm + mt * 16 + fRow) * 80 + (ks * 16 + fK) * 2;
                ldx4(ahf[mt], ra);
                ldx4(alf[mt], ra + R_AARR);
            }
            #pragma unroll
            for (int nt = 0; nt < 2; nt++) {
                const uint32_t rb = base + R_BOFF + (ks * 16 + tK) * 144 + (wn + nt * 16 + tN) * 2;
                ldx4t(bb[nt], rb);
            }
            #pragma unroll
            for (int mt = 0; mt < 2; mt++)
                #pragma unroll
                for (int nt = 0; nt < 2; nt++) {
                    mma16816(acc[mt][nt*2],   ahf[mt], bb[nt][0], bb[nt][1]);
                    mma16816(acc[mt][nt*2+1], ahf[mt], bb[nt][2], bb[nt][3]);
                    mma16816(acc[mt][nt*2],   alf[mt], bb[nt][0], bb[nt][1]);
                    mma16816(acc[mt][nt*2+1], alf[mt], bb[nt][2], bb[nt][3]);
                }
            #pragma unroll
            for (int nt = 0; nt < 2; nt++) {
                const uint32_t rb = base + R_BOFF + R_BARR + (ks * 16 + tK) * 144 + (wn + nt * 16 + tN) * 2;
                ldx4t(bb[nt], rb);
            }
            #pragma unroll
            for (int mt = 0; mt < 2; mt++)
                #pragma unroll
                for (int nt = 0; nt < 2; nt++) {
                    mma16816(acc[mt][nt*2],   ahf[mt], bb[nt][0], bb[nt][1]);
                    mma16816(acc[mt][nt*2+1], ahf[mt], bb[nt][2], bb[nt][3]);
                }
        }
        __syncthreads();
    }

    #pragma unroll
    for (int mt = 0; mt < 2; mt++)
        #pragma unroll
        for (int h = 0; h < 2; h++) {
            const int m = wm + mt * 16 + h * 8 + (lane >> 2);
            const int pos = (c & 15) * 64 + m;
            const float scale = rsqrtf((float)(pos + 1) * 64.0f);
            const long orow = ((long)c * 64 + m) * 512;
            #pragma unroll
            for (int n8 = 0; n8 < 4; n8++) {
                const int col = col0 + wn + n8 * 8 + (lane & 3) * 2;
                float2 o;
                o.x = acc[mt][n8][h*2+0] * scale;
                o.y = acc[mt][n8][h*2+1] * scale;
                *(float2*)&Out[orow + col] = o;
            }
        }
}

// ================= prep ====================================================
__global__ __launch_bounds__(256)
void prep_kernel(const float* __restrict__ x,
                 const float* __restrict__ W0, const float* __restrict__ W1,
                 const float* __restrict__ W2, const float* __restrict__ W3,
                 const float* __restrict__ Wk2, const float* __restrict__ Wq2,
                 bf16* __restrict__ xh, bf16* __restrict__ xl,
                 bf16* __restrict__ Wth, bf16* __restrict__ Wtl,
                 bf16* __restrict__ Wph, bf16* __restrict__ Wpl)
{
    const int bid = blockIdx.x, tid = threadIdx.x;
    if (bid < 1024) {
        const int i = bid * 256 + tid;
        float4 v = ((const float4*)x)[i];
        bsplit2(v.x, v.y, xh + i * 4,     xl + i * 4);
        bsplit2(v.z, v.w, xh + i * 4 + 2, xl + i * 4 + 2);
    } else if (bid < 2048) {
        const int widx = bid - 1024;
        const int z = widx >> 8, tile = widx & 255;
        const int k0 = (tile >> 4) * 32, n0 = (tile & 15) * 32;
        const float* W = z == 0 ? W0 : z == 1 ? W1 : z == 2 ? W2 : W3;
        __shared__ float t[32][33];
        #pragma unroll
        for (int j = 0; j < 4; j++) {
            const int r = (tid >> 5) + j * 8;
            t[r][tid & 31] = W[(long)(k0 + r) * 512 + n0 + (tid & 31)];
        }
        __syncthreads();
        #pragma unroll
        for (int j = 0; j < 4; j++) {
            const int nr = (tid >> 5) + j * 8, kc = tid & 31;
            const float v = t[kc][nr];
            const long o = (long)z * 262144 + (long)(n0 + nr) * 512 + k0 + kc;
            bf16 h = __float2bfloat16(v);
            Wth[o] = h;
            Wtl[o] = __float2bfloat16(v - __bfloat162float(h));
        }
    } else {
        const int widx = bid - 2048;
        const int z = widx >> 5, tile = widx & 31;
        const int k0 = (tile >> 1) * 32, n0 = (tile & 1) * 32;
        const float* W = z ? Wq2 : Wk2;
        __shared__ float t[32][33];
        #pragma unroll
        for (int j = 0; j < 4; j++) {
            const int r = (tid >> 5) + j * 8;
            t[r][tid & 31] = W[(long)(k0 + r) * 64 + n0 + (tid & 31)];
        }
        __syncthreads();
        #pragma unroll
        for (int j = 0; j < 4; j++) {
            const int nr = (tid >> 5) + j * 8, kc = tid & 31;
            const float v = t[kc][nr];
            const long o = (long)(z * 64 + n0 + nr) * 512 + k0 + kc;
            bf16 h = __float2bfloat16(v);
            Wph[o] = h;
            Wpl[o] = __float2bfloat16(v - __bfloat162float(h));
        }
    }
}

// ================= prefix ==================================================
__global__ __launch_bounds__(256)
void prefix_kernel(const float4* __restrict__ S, bf16* __restrict__ Ph,
                   bf16* __restrict__ Pl)
{
    int gidx = blockIdx.x * 256 + threadIdx.x;
    int b = gidx >> 14;
    int i = gidx & 16383;
    long base = (long)b * 16 * 16384 + i;
    float4 run = make_float4(0.f, 0.f, 0.f, 0.f);
    #pragma unroll
    for (int c = 0; c < 16; c++) {
        long idx = base + (long)c * 16384;
        long e = idx * 4;
        bsplit2(run.x, run.y, Ph + e,     Pl + e);
        bsplit2(run.z, run.w, Ph + e + 2, Pl + e + 2);
        float4 s = S[idx];
        run.x += s.x; run.y += s.y; run.z += s.z; run.w += s.w;
    }
}

// ================= LayerNorm (warp-per-row) ================================
__global__ __launch_bounds__(256)
void ln_kernel(const float* __restrict__ X, const float* __restrict__ gg,
               const float* __restrict__ bb, bf16* __restrict__ oh,
               bf16* __restrict__ ol)
{
    const int row = blockIdx.x * 8 + (threadIdx.x >> 5);
    const int lane = threadIdx.x & 31;
    const float4* Xr = (const float4*)(X + (long)row * 512);
    float4 v[4];
    float s = 0.f, sq = 0.f;
    #pragma unroll
    for (int q = 0; q < 4; q++) {
        v[q] = Xr[lane + 32 * q];
        s  += v[q].x + v[q].y + v[q].z + v[q].w;
        sq += v[q].x * v[q].x + v[q].y * v[q].y + v[q].z * v[q].z + v[q].w * v[q].w;
    }
    #pragma unroll
    for (int o = 16; o; o >>= 1) {
        s  += __shfl_xor_sync(0xFFFFFFFFu, s, o);
        sq += __shfl_xor_sync(0xFFFFFFFFu, sq, o);
    }
    const float mean = s * (1.0f / 512.0f);
    const float var  = sq * (1.0f / 512.0f) - mean * mean;
    const float rs   = rsqrtf(var + 1e-5f);
    #pragma unroll
    for (int q = 0; q < 4; q++) {
        const int idx = lane + 32 * q;
        float4 g4 = ((const float4*)gg)[idx];
        float4 b4 = ((const float4*)bb)[idx];
        float o0 = (v[q].x - mean) * rs * g4.x + b4.x;
        float o1 = (v[q].y - mean) * rs * g4.y + b4.y;
        float o2 = (v[q].z - mean) * rs * g4.z + b4.z;
        float o3 = (v[q].w - mean) * rs * g4.w + b4.w;
        long e = (long)row * 512 + idx * 4;
        bsplit2(o0, o1, oh + e,     ol + e);
        bsplit2(o2, o3, oh + e + 2, ol + e + 2);
    }
}

// ================= launch =================
extern "C" void kernel_launch(void* const* d_in, const int* in_sizes, int n_in,
                              void* d_out, int out_size)
{
    const float* x    = (const float*)d_in[0];
    const float* Wk1  = (const float*)d_in[1];
    const float* bk1  = (const float*)d_in[2];
    const float* Wk2  = (const float*)d_in[3];
    const float* bk2  = (const float*)d_in[4];
    const float* Wq1  = (const float*)d_in[5];
    const float* bq1  = (const float*)d_in[6];
    const float* Wq2  = (const float*)d_in[7];
    const float* bq2  = (const float*)d_in[8];
    const float* Wv   = (const float*)d_in[9];
    const float* bv   = (const float*)d_in[10];
    const float* ln_g = (const float*)d_in[11];
    const float* ln_b = (const float*)d_in[12];
    const float* Wo   = (const float*)d_in[13];
    const float* bo   = (const float*)d_in[14];
    float* out = (float*)d_out;

    void* p;
    cudaGetSymbolAddress(&p, g_xh);    bf16* xh    = (bf16*)p;
    cudaGetSymbolAddress(&p, g_xl);    bf16* xl    = (bf16*)p;
    cudaGetSymbolAddress(&p, g_Wth);   bf16* Wth   = (bf16*)p;
    cudaGetSymbolAddress(&p, g_Wtl);   bf16* Wtl   = (bf16*)p;
    cudaGetSymbolAddress(&p, g_Wph);   bf16* Wph   = (bf16*)p;
    cudaGetSymbolAddress(&p, g_Wpl);   bf16* Wpl   = (bf16*)p;
    cudaGetSymbolAddress(&p, g_Hkh);   bf16* Hkh   = (bf16*)p;
    cudaGetSymbolAddress(&p, g_Hkl);   bf16* Hkl   = (bf16*)p;
    cudaGetSymbolAddress(&p, g_Hqh);   bf16* Hqh   = (bf16*)p;
    cudaGetSymbolAddress(&p, g_Hql);   bf16* Hql   = (bf16*)p;
    cudaGetSymbolAddress(&p, g_Vh);    bf16* Vh    = (bf16*)p;
    cudaGetSymbolAddress(&p, g_Vl);    bf16* Vl    = (bf16*)p;
    cudaGetSymbolAddress(&p, g_CSkh);  bf16* CSkh  = (bf16*)p;
    cudaGetSymbolAddress(&p, g_CSkl);  bf16* CSkl  = (bf16*)p;
    cudaGetSymbolAddress(&p, g_CSqh);  bf16* CSqh  = (bf16*)p;
    cudaGetSymbolAddress(&p, g_CSql);  bf16* CSql  = (bf16*)p;
    cudaGetSymbolAddress(&p, g_CSkTh); bf16* CSkTh = (bf16*)p;
    cudaGetSymbolAddress(&p, g_CSkTl); bf16* CSkTl = (bf16*)p;
    cudaGetSymbolAddress(&p, g_Ach);   bf16* Ach   = (bf16*)p;
    cudaGetSymbolAddress(&p, g_Acl);   bf16* Acl   = (bf16*)p;
    cudaGetSymbolAddress(&p, g_S);     float* S    = (float*)p;
    cudaGetSymbolAddress(&p, g_Ph);    bf16* Ph    = (bf16*)p;
    cudaGetSymbolAddress(&p, g_Pl);    bf16* Pl    = (bf16*)p;
    cudaGetSymbolAddress(&p, g_R);     float* R    = (float*)p;
    cudaGetSymbolAddress(&p, g_LNh);   bf16* LNh   = (bf16*)p;
    cudaGetSymbolAddress(&p, g_LNl);   bf16* LNl   = (bf16*)p;

    static int attr_set = 0;
    if (!attr_set) {
        cudaFuncSetAttribute(mma_gemm<0>, cudaFuncAttributeMaxDynamicSharedMemorySize, X0_SMEM);
        cudaFuncSetAttribute(mma_gemm<1>, cudaFuncAttributeMaxDynamicSharedMemorySize, X1_SMEM);
        cudaFuncSetAttribute(phase_mma,   cudaFuncAttributeMaxDynamicSharedMemorySize, P_SMEM);
        cudaFuncSetAttribute(sac_mma,     cudaFuncAttributeMaxDynamicSharedMemorySize, SAC_SMEM);
        cudaFuncSetAttribute(r_mma,       cudaFuncAttributeMaxDynamicSharedMemorySize, R_SMEM);
        attr_set = 1;
    }

    // 0) conversions
    prep_kernel<<<2112, 256>>>(x, Wk1, Wq1, Wv, Wo, Wk2, Wq2,
                               xh, xl, Wth, Wtl, Wph, Wpl);

    // 1) XW: Hk(gelu), Hq(gelu), V(bias). grid (4,32,3)=384 (R12 config).
    mma_gemm<0><<<dim3(4,32,3), 128, X0_SMEM>>>(
        xh, xl, Wth, Wtl, bk1, bq1, bv, nullptr,
        Hkh, Hkl, Hqh, Hql, Vh, Vl, nullptr);

    // 2) Phases (split-K, 16-row tiles). grid (1,128,2)=256.
    phase_mma<<<dim3(1,128,2), 256, P_SMEM>>>(
        Hkh, Hkl, Hqh, Hql, Wph, Wpl, bk2, bq2,
        CSkh, CSkl, CSqh, CSql, CSkTh, CSkTl);

    // 3) S + Ac. grid (9,1,32)=288.
    sac_mma<<<dim3(9,1,32), 256, SAC_SMEM>>>(
        CSkTh, CSkTl, Vh, Vl, CSqh, CSql, CSkh, CSkl, S, Ach, Acl);

    // 4) exclusive prefix -> split bf16 P
    prefix_kernel<<<128, 256>>>((const float4*)S, Ph, Pl);

    // 5) R. grid (8,1,32)=256.
    r_mma<<<dim3(8,1,32), 128, R_SMEM>>>(
        CSqh, CSql, Ach, Acl, Ph, Pl, Vh, Vl, R);

    // 6) LN -> split bf16 (warp-per-row)
    ln_kernel<<<256, 256>>>(R, ln_g, ln_b, LNh, LNl);

    // 7) out = x + LN @ Wo + bo. grid (8,32)=256 (R12 config).
    mma_gemm<1><<<dim3(8,32,1), 128, X1_SMEM>>>(
        LNh, LNl, Wth + 3L*262144, Wtl + 3L*262144, bo, nullptr, nullptr, x,
        nullptr, nullptr, nullptr, nullptr, nullptr, nullptr, out);
}

// round 15
// speedup vs baseline: 1.0287x; 1.0237x over previous
#include <cuda_runtime.h>
#include <cuda_bf16.h>
#include <math.h>
#include <stdint.h>

#define PI_F 3.14159265358979323846f
typedef __nv_bfloat16 bf16;

// PDL: wait for upstream kernel's data before consuming (sm_90+)
#define GDS() asm volatile("griddepcontrol.wait;" ::: "memory")

// ---------------- scratch ----------------
__device__ bf16 g_xh  [2048 * 512];
__device__ bf16 g_xl  [2048 * 512];
__device__ bf16 g_Wth [4 * 512 * 512];
__device__ bf16 g_Wtl [4 * 512 * 512];
__device__ bf16 g_Wph [128 * 512];
__device__ bf16 g_Wpl [128 * 512];
__device__ bf16 g_Hkh [2048 * 512];
__device__ bf16 g_Hkl [2048 * 512];
__device__ bf16 g_Hqh [2048 * 512];
__device__ bf16 g_Hql [2048 * 512];
__device__ bf16 g_Vh  [2048 * 512];
__device__ bf16 g_Vl  [2048 * 512];
__device__ bf16 g_CSkh[2048 * 128];
__device__ bf16 g_CSkl[2048 * 128];
__device__ bf16 g_CSqh[2048 * 128];
__device__ bf16 g_CSql[2048 * 128];
__device__ bf16 g_CSkTh[32 * 128 * 64];
__device__ bf16 g_CSkTl[32 * 128 * 64];
__device__ bf16 g_Ach [32 * 64 * 64];
__device__ bf16 g_Acl [32 * 64 * 64];
__device__ float g_S  [32 * 128 * 512];
__device__ bf16 g_Ph  [32 * 128 * 512];
__device__ bf16 g_Pl  [32 * 128 * 512];
__device__ float g_R  [2048 * 512];
__device__ bf16 g_LNh [2048 * 512];
__device__ bf16 g_LNl [2048 * 512];

// ================= PTX helpers =================
__device__ __forceinline__ uint32_t smem_u32(const void* p) {
    uint32_t a;
    asm("{ .reg .u64 t; cvta.to.shared.u64 t, %1; cvt.u32.u64 %0, t; }" : "=r"(a) : "l"(p));
    return a;
}
__device__ __forceinline__ void cp16(uint32_t dst, const void* src) {
    asm volatile("cp.async.cg.shared.global [%0], [%1], 16;" :: "r"(dst), "l"(src));
}
__device__ __forceinline__ void ldx4(uint32_t* r, uint32_t addr) {
    asm volatile("ldmatrix.sync.aligned.m8n8.x4.shared.b16 {%0,%1,%2,%3}, [%4];"
        : "=r"(r[0]), "=r"(r[1]), "=r"(r[2]), "=r"(r[3]) : "r"(addr));
}
__device__ __forceinline__ void ldx4t(uint32_t* r, uint32_t addr) {
    asm volatile("ldmatrix.sync.aligned.m8n8.x4.trans.shared.b16 {%0,%1,%2,%3}, [%4];"
        : "=r"(r[0]), "=r"(r[1]), "=r"(r[2]), "=r"(r[3]) : "r"(addr));
}
__device__ __forceinline__ void mma16816(float* c, const uint32_t* a,
                                         uint32_t b0, uint32_t b1) {
    asm volatile("mma.sync.aligned.m16n8k16.row.col.f32.bf16.bf16.f32 "
        "{%0,%1,%2,%3}, {%4,%5,%6,%7}, {%8,%9}, {%0,%1,%2,%3};"
        : "+f"(c[0]), "+f"(c[1]), "+f"(c[2]), "+f"(c[3])
        : "r"(a[0]), "r"(a[1]), "r"(a[2]), "r"(a[3]), "r"(b0), "r"(b1));
}
__device__ __forceinline__ void bsplit2(float v0, float v1, bf16* hd, bf16* ld) {
    __nv_bfloat162 h, l;
    h.x = __float2bfloat16(v0); h.y = __float2bfloat16(v1);
    l.x = __float2bfloat16(v0 - __bfloat162float(h.x));
    l.y = __float2bfloat16(v1 - __bfloat162float(h.y));
    *(__nv_bfloat162*)hd = h; *(__nv_bfloat162*)ld = l;
}
#define CPA_COMMIT() asm volatile("cp.async.commit_group;" ::: "memory")
#define CPA_WAIT1()  asm volatile("cp.async.wait_group 1;" ::: "memory")
#define CPA_WAIT0()  asm volatile("cp.async.wait_group 0;" ::: "memory")

// ================= XW / OUT GEMM: 64xBN tile, 128 thr, 4 warps (2m x 2n) ====
static constexpr int XA_ARR = 64 * 80;
static constexpr int XB_OFF = 2 * XA_ARR;
static constexpr int X0_SMEM = 2 * (XB_OFF + 2 * 128 * 80);  // 61440
static constexpr int X1_SMEM = 2 * (XB_OFF + 2 * 64 * 80);   // 40960

template<int MODE>   // 0: BN=128 XW (split bf16 out, gelu z<2); 1: BN=64 fp32+resid
__global__ __launch_bounds__(128, 3)
void mma_gemm(const bf16* __restrict__ Ah, const bf16* __restrict__ Al,
              const bf16* __restrict__ Wth, const bf16* __restrict__ Wtl,
              const float* __restrict__ b0, const float* __restrict__ b1,
              const float* __restrict__ b2, const float* __restrict__ resid,
              bf16* __restrict__ O0h, bf16* __restrict__ O0l,
              bf16* __restrict__ O1h, bf16* __restrict__ O1l,
              bf16* __restrict__ O2h, bf16* __restrict__ O2l,
              float* __restrict__ Cout)
{
    constexpr int BN = (MODE == 0) ? 128 : 64;
    constexpr int NT = BN / 32;
    constexpr int XB_ARR = BN * 80;
    constexpr int X_BUF  = XB_OFF + 2 * XB_ARR;
    constexpr int BLD = BN / 16;

    GDS();
    extern __shared__ __align__(128) char smem[];
    const uint32_t sb = smem_u32(smem);
    const int tid = threadIdx.x, wid = tid >> 5, lane = tid & 31;
    const int row0 = blockIdx.y * 64, col0 = blockIdx.x * BN;
    const int z = (MODE == 0) ? (int)blockIdx.z : 0;
    const bf16* Bh = Wth + (long)z * 262144;
    const bf16* Bl = Wtl + (long)z * 262144;
    const float* bias = (z == 0) ? b0 : (z == 1 ? b1 : b2);
    const bool gelu = (MODE == 0) && (z < 2);
    bf16* Oh = (z == 0) ? O0h : (z == 1 ? O1h : O2h);
    bf16* Ol = (z == 0) ? O0l : (z == 1 ? O1l : O2l);

    const int wm = (wid & 1) * 32, wn = (wid >> 1) * (BN / 2);
    float acc[2][2 * NT][4];
    #pragma unroll
    for (int i = 0; i < 2; i++)
        #pragma unroll
        for (int j = 0; j < 2 * NT; j++)
            #pragma unroll
            for (int e = 0; e < 4; e++) acc[i][j][e] = 0.0f;

    const int g = lane >> 3, wr = lane & 7;
    const int fRow = wr + (g & 1) * 8, fK = (g >> 1) * 8;

    auto load_chunk = [&](int ch, int b) {
        const int k0 = ch * 32;
        const uint32_t base = sb + b * X_BUF;
        #pragma unroll
        for (int l = 0; l < 4; l++) {
            const int idx = tid + l * 128;
            const int arr = idx >> 8, rr = (idx >> 2) & 63, s = idx & 3;
            cp16(base + arr * XA_ARR + rr * 80 + s * 16,
                 (arr ? Al : Ah) + (long)(row0 + rr) * 512 + k0 + s * 8);
        }
        #pragma unroll
        for (int l = 0; l < BLD; l++) {
            const int idx = tid + l * 128;
            const int arr = idx / (BN * 4), rr = (idx >> 2) % BN, s = idx & 3;
            cp16(base + XB_OFF + arr * XB_ARR + rr * 80 + s * 16,
                 (arr ? Bl : Bh) + (long)(col0 + rr) * 512 + k0 + s * 8);
        }
        CPA_COMMIT();
    };

    load_chunk(0, 0);
    for (int ch = 0; ch < 16; ch++) {
        const int b = ch & 1;
        if (ch < 15) { load_chunk(ch + 1, b ^ 1); CPA_WAIT1(); }
        else CPA_WAIT0();
        __syncthreads();
        const uint32_t base = sb + b * X_BUF;
        #pragma unroll
        for (int ks = 0; ks < 2; ks++) {
            uint32_t ahf[2][4], alf[2][4], bb[NT][4];
            #pragma unroll
            for (int mt = 0; mt < 2; mt++) {
                const uint32_t ra = base + (wm + mt * 16 + fRow) * 80 + (ks * 16 + fK) * 2;
                ldx4(ahf[mt], ra);
                ldx4(alf[mt], ra + XA_ARR);
            }
            #pragma unroll
            for (int nt = 0; nt < NT; nt++) {
                const uint32_t rb = base + XB_OFF + (wn + nt * 16 + fRow) * 80 + (ks * 16 + fK) * 2;
                ldx4(bb[nt], rb);
            }
            #pragma unroll
            for (int mt = 0; mt < 2; mt++)
                #pragma unroll
                for (int nt = 0; nt < NT; nt++) {
                    mma16816(acc[mt][nt*2],   ahf[mt], bb[nt][0], bb[nt][2]);
                    mma16816(acc[mt][nt*2+1], ahf[mt], bb[nt][1], bb[nt][3]);
                    mma16816(acc[mt][nt*2],   alf[mt], bb[nt][0], bb[nt][2]);
                    mma16816(acc[mt][nt*2+1], alf[mt], bb[nt][1], bb[nt][3]);
                }
            #pragma unroll
            for (int nt = 0; nt < NT; nt++) {
                const uint32_t rb = base + XB_OFF + XB_ARR + (wn + nt * 16 + fRow) * 80 + (ks * 16 + fK) * 2;
                ldx4(bb[nt], rb);
            }
            #pragma unroll
            for (int mt = 0; mt < 2; mt++)
                #pragma unroll
                for (int nt = 0; nt < NT; nt++) {
                    mma16816(acc[mt][nt*2],   ahf[mt], bb[nt][0], bb[nt][2]);
                    mma16816(acc[mt][nt*2+1], ahf[mt], bb[nt][1], bb[nt][3]);
                }
        }
        __syncthreads();
    }

    #pragma unroll
    for (int mt = 0; mt < 2; mt++)
        #pragma unroll
        for (int h = 0; h < 2; h++) {
            const int row = row0 + wm + mt * 16 + h * 8 + (lane >> 2);
            #pragma unroll
            for (int n8 = 0; n8 < 2 * NT; n8++) {
                const int col = col0 + wn + n8 * 8 + (lane & 3) * 2;
                float v0 = acc[mt][n8][h * 2 + 0];
                float v1 = acc[mt][n8][h * 2 + 1];
                const float2 bq = *(const float2*)&bias[col];
                v0 += bq.x; v1 += bq.y;
                if (MODE == 0) {
                    if (gelu) {
                        v0 = 0.5f * v0 * (1.0f + erff(v0 * 0.70710678118654752f));
                        v1 = 0.5f * v1 * (1.0f + erff(v1 * 0.70710678118654752f));
                    }
                    bsplit2(v0, v1, Oh + (long)row * 512 + col, Ol + (long)row * 512 + col);
                } else {
                    const float2 r2 = *(const float2*)&resid[(long)row * 512 + col];
                    float2 o; o.x = v0 + r2.x; o.y = v1 + r2.y;
                    *(float2*)&Cout[(long)row * 512 + col] = o;
                }
            }
        }
}

// ================= phase GEMM: 32x64 tile, 256 thr, split-K (2 groups) =====
static constexpr int PH_A    = 32 * 80;
static constexpr int PH_HALF = 2 * PH_A + 2 * 64 * 80;
static constexpr int PH_STG  = 2 * PH_HALF;
static constexpr int P_SMEM  = 2 * PH_STG;   // 61440

__global__ __launch_bounds__(256)
void phase_mma(const bf16* __restrict__ Hkh, const bf16* __restrict__ Hkl,
               const bf16* __restrict__ Hqh, const bf16* __restrict__ Hql,
               const bf16* __restrict__ Wph, const bf16* __restrict__ Wpl,
               const float* __restrict__ bk2, const float* __restrict__ bq2,
               bf16* __restrict__ CSkh, bf16* __restrict__ CSkl,
               bf16* __restrict__ CSqh, bf16* __restrict__ CSql,
               bf16* __restrict__ CSkTh, bf16* __restrict__ CSkTl)
{
    GDS();
    extern __shared__ __align__(128) char smem[];
    const uint32_t sb = smem_u32(smem);
    const int tid = threadIdx.x, wid = tid >> 5, lane = tid & 31;
    const int z = blockIdx.z, row0 = blockIdx.y * 32;
    const bf16* Ah = z ? Hqh : Hkh;
    const bf16* Al = z ? Hql : Hkl;
    const bf16* Bh = Wph + (long)z * 64 * 512;
    const bf16* Bl = Wpl + (long)z * 64 * 512;
    const float* bias = z ? bq2 : bk2;

    const int grp = wid >> 2;
    const int wid2 = wid & 3;
    const int wm = (wid2 & 1) * 16, wn = (wid2 >> 1) * 32;
    float acc[4][4];
    #pragma unroll
    for (int j = 0; j < 4; j++)
        #pragma unroll
        for (int e = 0; e < 4; e++) acc[j][e] = 0.0f;

    const int g = lane >> 3, wr = lane & 7;
    const int fRow = wr + (g & 1) * 8, fK = (g >> 1) * 8;

    auto load_chunk = [&](int ch) {
        const int k0 = ch * 32;
        const uint32_t base = sb + (ch & 1) * PH_STG;
        #pragma unroll
        for (int l = 0; l < 2; l++) {
            const int idx = tid + l * 256;
            const int hf = idx >> 8, ii = idx & 255;
            const int arr = ii >> 7, pos = ii & 127, rr = pos >> 2, s = pos & 3;
            cp16(base + hf * PH_HALF + arr * PH_A + rr * 80 + s * 16,
                 (arr ? Al : Ah) + (long)(row0 + rr) * 512 + hf * 256 + k0 + s * 8);
        }
        #pragma unroll
        for (int l = 0; l < 4; l++) {
            const int idx = tid + l * 256;
            const int hf = idx >> 9, ii = idx & 511;
            const int arr = ii >> 8, pos = ii & 255, rr = pos >> 2, s = pos & 3;
            cp16(base + hf * PH_HALF + 2 * PH_A + arr * 5120 + rr * 80 + s * 16,
                 (arr ? Bl : Bh) + (long)rr * 512 + hf * 256 + k0 + s * 8);
        }
        CPA_COMMIT();
    };

    load_chunk(0);
    for (int ch = 0; ch < 8; ch++) {
        if (ch < 7) { load_chunk(ch + 1); CPA_WAIT1(); }
        else CPA_WAIT0();
        __syncthreads();
        const uint32_t hbase = sb + (ch & 1) * PH_STG + grp * PH_HALF;
        #pragma unroll
        for (int ks = 0; ks < 2; ks++) {
            uint32_t ahf[4], alf[4], bb[2][4];
            {
                const uint32_t ra = hbase + (wm + fRow) * 80 + (ks * 16 + fK) * 2;
                ldx4(ahf, ra);
                ldx4(alf, ra + PH_A);
            }
            #pragma unroll
            for (int nt = 0; nt < 2; nt++) {
                const uint32_t rb = hbase + 2 * PH_A + (wn + nt * 16 + fRow) * 80 + (ks * 16 + fK) * 2;
                ldx4(bb[nt], rb);
            }
            #pragma unroll
            for (int nt = 0; nt < 2; nt++) {
                mma16816(acc[nt*2],   ahf, bb[nt][0], bb[nt][2]);
                mma16816(acc[nt*2+1], ahf, bb[nt][1], bb[nt][3]);
                mma16816(acc[nt*2],   alf, bb[nt][0], bb[nt][2]);
                mma16816(acc[nt*2+1], alf, bb[nt][1], bb[nt][3]);
            }
            #pragma unroll
            for (int nt = 0; nt < 2; nt++) {
                const uint32_t rb = hbase + 2 * PH_A + 5120 + (wn + nt * 16 + fRow) * 80 + (ks * 16 + fK) * 2;
                ldx4(bb[nt], rb);
            }
            #pragma unroll
            for (int nt = 0; nt < 2; nt++) {
                mma16816(acc[nt*2],   ahf, bb[nt][0], bb[nt][2]);
                mma16816(acc[nt*2+1], ahf, bb[nt][1], bb[nt][3]);
            }
        }
        __syncthreads();
    }

    float* red = (float*)smem;
    #pragma unroll
    for (int j = 0; j < 4; j++)
        *(float4*)&red[tid * 16 + j * 4] = *(float4*)acc[j];
    __syncthreads();
    if (tid < 128) {
        #pragma unroll
        for (int j = 0; j < 4; j++) {
            float4 o = *(float4*)&red[(tid + 128) * 16 + j * 4];
            acc[j][0] += o.x; acc[j][1] += o.y; acc[j][2] += o.z; acc[j][3] += o.w;
        }
        #pragma unroll
        for (int h = 0; h < 2; h++) {
            const int row = row0 + wm + h * 8 + (lane >> 2);
            #pragma unroll
            for (int j = 0; j < 4; j++) {
                const int n = wn + (j >> 1) * 16 + (j & 1) * 8 + (lane & 3) * 2;
                float v0 = acc[j][h * 2 + 0] + bias[n];
                float v1 = acc[j][h * 2 + 1] + bias[n + 1];
                float p0 = tanhf(v0) * PI_F, p1 = tanhf(v1) * PI_F;
                float c0, s0, c1, s1;
                sincosf(p0, &s0, &c0);
                sincosf(p1, &s1, &c1);
                bf16* Rh = z ? CSqh : CSkh;
                bf16* Rl = z ? CSql : CSkl;
                const long rb_ = (long)row * 128;
                bsplit2(c0, c1, Rh + rb_ + n,      Rl + rb_ + n);
                bsplit2(s0, s1, Rh + rb_ + n + 64, Rl + rb_ + n + 64);
                if (!z) {
                    const int c = row >> 6, ro = row & 63;
                    const long t0 = (long)c * 8192 + (long)n * 64 + ro;
                    bf16 h0 = __float2bfloat16(c0);
                    bf16 h1 = __float2bfloat16(c1);
                    bf16 h2 = __float2bfloat16(s0);
                    bf16 h3 = __float2bfloat16(s1);
                    CSkTh[t0]        = h0;
                    CSkTh[t0 + 64]   = h1;
                    CSkTh[t0 + 4096] = h2;
                    CSkTh[t0 + 4160] = h3;
                    CSkTl[t0]        = __float2bfloat16(c0 - __bfloat162float(h0));
                    CSkTl[t0 + 64]   = __float2bfloat16(c1 - __bfloat162float(h1));
                    CSkTl[t0 + 4096] = __float2bfloat16(s0 - __bfloat162float(h2));
                    CSkTl[t0 + 4160] = __float2bfloat16(s1 - __bfloat162float(h3));
                }
            }
        }
    }
}

// ================= S + Ac combined launch ==================================
static constexpr int S_AARR = 128 * 80;
static constexpr int S_BOFF = 2 * S_AARR;
static constexpr int S_BARR = 32 * 144;
static constexpr int S_BUF  = S_BOFF + 2 * S_BARR;
static constexpr int SAC_SMEM = 2 * S_BUF;
static constexpr int AC_AARR = 64 * 80;
static constexpr int AC_BOFF = 2 * AC_AARR;
static constexpr int AC_BUF  = 2 * AC_BOFF;

__global__ __launch_bounds__(256)
void sac_mma(const bf16* __restrict__ CSkTh, const bf16* __restrict__ CSkTl,
             const bf16* __restrict__ Vh, const bf16* __restrict__ Vl,
             const bf16* __restrict__ CSqh, const bf16* __restrict__ CSql,
             const bf16* __restrict__ CSkh, const bf16* __restrict__ CSkl,
             float* __restrict__ S, bf16* __restrict__ Ach, bf16* __restrict__ Acl)
{
    GDS();
    extern __shared__ __align__(128) char smem[];
    const uint32_t sb = smem_u32(smem);
    const int tid = threadIdx.x, wid = tid >> 5, lane = tid & 31;
    const int c = blockIdx.z;
    const int g = lane >> 3, wr = lane & 7;
    const int fRow = wr + (g & 1) * 8, fK = (g >> 1) * 8;
    const int tK = fRow, tN = (g >> 1) * 8;

    if (blockIdx.x < 8) {
        const int col0 = blockIdx.x * 64;
        const int wm = (wid & 3) * 32, wn = (wid >> 2) * 32;
        float acc[2][4][4];
        #pragma unroll
        for (int i = 0; i < 2; i++)
            #pragma unroll
            for (int j = 0; j < 4; j++)
                #pragma unroll
                for (int e = 0; e < 4; e++) acc[i][j][e] = 0.0f;

        auto load_chunk = [&](int ch, int b) {
            const int k0 = ch * 32;
            const uint32_t base = sb + b * S_BUF;
            #pragma unroll
            for (int l = 0; l < 4; l++) {
                const int idx = tid + l * 256;
                const int arr = idx >> 9, rr = (idx >> 2) & 127, s = idx & 3;
                cp16(base + arr * S_AARR + rr * 80 + s * 16,
                     (arr ? CSkTl : CSkTh) + (long)c * 8192 + (long)rr * 64 + k0 + s * 8);
            }
            #pragma unroll
            for (int l = 0; l < 2; l++) {
                const int idx = tid + l * 256;
                const int arr = idx >> 8, rr = (idx >> 3) & 31, s = idx & 7;
                cp16(base + S_BOFF + arr * S_BARR + rr * 144 + s * 16,
                     (arr ? Vl : Vh) + ((long)c * 64 + k0 + rr) * 512 + col0 + s * 8);
            }
            CPA_COMMIT();
        };

        load_chunk(0, 0);
        load_chunk(1, 1);
        for (int ch = 0; ch < 2; ch++) {
            if (ch == 0) CPA_WAIT1(); else CPA_WAIT0();
            __syncthreads();
            const uint32_t base = sb + ch * S_BUF;
            #pragma unroll
            for (int ks = 0; ks < 2; ks++) {
                uint32_t ahf[2][4], alf[2][4], bb[2][4];
                #pragma unroll
                for (int mt = 0; mt < 2; mt++) {
                    const uint32_t ra = base + (wm + mt * 16 + fRow) * 80 + (ks * 16 + fK) * 2;
                    ldx4(ahf[mt], ra);
                    ldx4(alf[mt], ra + S_AARR);
                }
                #pragma unroll
                for (int nt = 0; nt < 2; nt++) {
                    const uint32_t rb = base + S_BOFF + (ks * 16 + tK) * 144 + (wn + nt * 16 + tN) * 2;
                    ldx4t(bb[nt], rb);
                }
                #pragma unroll
                for (int mt = 0; mt < 2; mt++)
                    #pragma unroll
                    for (int nt = 0; nt < 2; nt++) {
                        mma16816(acc[mt][nt*2],   ahf[mt], bb[nt][0], bb[nt][1]);
                        mma16816(acc[mt][nt*2+1], ahf[mt], bb[nt][2], bb[nt][3]);
                        mma16816(acc[mt][nt*2],   alf[mt], bb[nt][0], bb[nt][1]);
                        mma16816(acc[mt][nt*2+1], alf[mt], bb[nt][2], bb[nt][3]);
                    }
                #pragma unroll
                for (int nt = 0; nt < 2; nt++) {
                    const uint32_t rb = base + S_BOFF + S_BARR + (ks * 16 + tK) * 144 + (wn + nt * 16 + tN) * 2;
                    ldx4t(bb[nt], rb);
                }
                #pragma unroll
                for (int mt = 0; mt < 2; mt++)
                    #pragma unroll
                    for (int nt = 0; nt < 2; nt++) {
                        mma16816(acc[mt][nt*2],   ahf[mt], bb[nt][0], bb[nt][1]);
                        mma16816(acc[mt][nt*2+1], ahf[mt], bb[nt][2], bb[nt][3]);
                    }
            }
            __syncthreads();
        }

        #pragma unroll
        for (int mt = 0; mt < 2; mt++)
            #pragma unroll
            for (int h = 0; h < 2; h++) {
                const int m = wm + mt * 16 + h * 8 + (lane >> 2);
                const long orow = (long)c * 65536 + (long)m * 512;
                #pragma unroll
                for (int n8 = 0; n8 < 4; n8++) {
                    const int col = col0 + wn + n8 * 8 + (lane & 3) * 2;
                    float2 o; o.x = acc[mt][n8][h*2+0]; o.y = acc[mt][n8][h*2+1];
                    *(float2*)&S[orow + col] = o;
                }
            }
    } else {
        const int wm = (wid & 1) * 32, wn = (wid >> 1) * 16;
        float acc[2][2][4];
        #pragma unroll
        for (int i = 0; i < 2; i++)
            #pragma unroll
            for (int j = 0; j < 2; j++)
                #pragma unroll
                for (int e = 0; e < 4; e++) acc[i][j][e] = 0.0f;

        auto load_chunk = [&](int ch, int b) {
            const int k0 = ch * 32;
            const uint32_t base = sb + b * AC_BUF;
            #pragma unroll
            for (int l = 0; l < 2; l++) {
                const int idx = tid + l * 256;
                const int arr = idx >> 8, rr = (idx >> 2) & 63, s = idx & 3;
                cp16(base + arr * AC_AARR + rr * 80 + s * 16,
                     (arr ? CSql : CSqh) + ((long)c * 64 + rr) * 128 + k0 + s * 8);
            }
            #pragma unroll
            for (int l = 0; l < 2; l++) {
                const int idx = tid + l * 256;
                const int arr = idx >> 8, rr = (idx >> 2) & 63, s = idx & 3;
                cp16(base + AC_BOFF + arr * AC_AARR + rr * 80 + s * 16,
                     (arr ? CSkl : CSkh) + ((long)c * 64 + rr) * 128 + k0 + s * 8);
            }
            CPA_COMMIT();
        };

        load_chunk(0, 0);
        for (int ch = 0; ch < 4; ch++) {
            const int b = ch & 1;
            if (ch < 3) { load_chunk(ch + 1, b ^ 1); CPA_WAIT1(); }
            else CPA_WAIT0();
            __syncthreads();
            const uint32_t base = sb + b * AC_BUF;
            #pragma unroll
            for (int ks = 0; ks < 2; ks++) {
                uint32_t ahf[2][4], alf[2][4], bb[4];
                #pragma unroll
                for (int mt = 0; mt < 2; mt++) {
                    const uint32_t ra = base + (wm + mt * 16 + fRow) * 80 + (ks * 16 + fK) * 2;
                    ldx4(ahf[mt], ra);
                    ldx4(alf[mt], ra + AC_AARR);
                }
                {
                    const uint32_t rb = base + AC_BOFF + (wn + fRow) * 80 + (ks * 16 + fK) * 2;
                    ldx4(bb, rb);
                }
                #pragma unroll
                for (int mt = 0; mt < 2; mt++) {
                    mma16816(acc[mt][0], ahf[mt], bb[0], bb[2]);
                    mma16816(acc[mt][1], ahf[mt], bb[1], bb[3]);
                    mma16816(acc[mt][0], alf[mt], bb[0], bb[2]);
                    mma16816(acc[mt][1], alf[mt], bb[1], bb[3]);
                }
                {
                    const uint32_t rb = base + AC_BOFF + AC_AARR + (wn + fRow) * 80 + (ks * 16 + fK) * 2;
                    ldx4(bb, rb);
                }
                #pragma unroll
                for (int mt = 0; mt < 2; mt++) {
                    mma16816(acc[mt][0], ahf[mt], bb[0], bb[2]);
                    mma16816(acc[mt][1], ahf[mt], bb[1], bb[3]);
                }
            }
            __syncthreads();
        }

        #pragma unroll
        for (int mt = 0; mt < 2; mt++)
            #pragma unroll
            for (int h = 0; h < 2; h++) {
                const int row = wm + mt * 16 + h * 8 + (lane >> 2);
                #pragma unroll
                for (int n8 = 0; n8 < 2; n8++) {
                    const int col = wn + n8 * 8 + (lane & 3) * 2;
                    float v0 = (col     <= row) ? acc[mt][n8][h*2+0] : 0.0f;
                    float v1 = (col + 1 <= row) ? acc[mt][n8][h*2+1] : 0.0f;
                    const long o = (long)c * 4096 + (long)row * 64 + col;
                    bsplit2(v0, v1, Ach + o, Acl + o);
                }
            }
    }
}

// ================= R GEMM: M64,N64,K192, 128 thr ===========================
static constexpr int R_AARR = 64 * 80;
static constexpr int R_BOFF = 2 * R_AARR;
static constexpr int R_BARR = 32 * 144;
static constexpr int R_BUF  = R_BOFF + 2 * R_BARR;
static constexpr int R_SMEM = 3 * R_BUF;

__global__ __launch_bounds__(128)
void r_mma(const bf16* __restrict__ CSqh, const bf16* __restrict__ CSql,
           const bf16* __restrict__ Ach, const bf16* __restrict__ Acl,
           const bf16* __restrict__ Ph, const bf16* __restrict__ Pl,
           const bf16* __restrict__ Vh, const bf16* __restrict__ Vl,
           float* __restrict__ Out)
{
    GDS();
    extern __shared__ __align__(128) char smem[];
    const uint32_t sb = smem_u32(smem);
    const int tid = threadIdx.x, wid = tid >> 5, lane = tid & 31;
    const int c = blockIdx.z, col0 = blockIdx.x * 64;
    const int wm = (wid & 1) * 32, wn = (wid >> 1) * 32;
    const int g = lane >> 3, wr = lane & 7;
    const int fRow = wr + (g & 1) * 8, fK = (g >> 1) * 8;
    const int tK = fRow, tN = (g >> 1) * 8;

    float acc[2][4][4];
    #pragma unroll
    for (int i = 0; i < 2; i++)
        #pragma unroll
        for (int j = 0; j < 4; j++)
            #pragma unroll
            for (int e = 0; e < 4; e++) acc[i][j][e] = 0.0f;

    auto load_chunk = [&](int ch) {
        const uint32_t base = sb + (ch % 3) * R_BUF;
        const bf16 *aH, *aL, *bH, *bL;
        int ldA, k0;
        long rowB;
        if (ch < 4) {
            aH = CSqh + (long)c * 8192; aL = CSql + (long)c * 8192;
            ldA = 128; k0 = ch * 32;
            bH = Ph; bL = Pl; rowB = (long)c * 128 + ch * 32;
        } else {
            aH = Ach + (long)c * 4096; aL = Acl + (long)c * 4096;
            ldA = 64; k0 = (ch - 4) * 32;
            bH = Vh; bL = Vl; rowB = (long)c * 64 + (ch - 4) * 32;
        }
        #pragma unroll
        for (int l = 0; l < 4; l++) {
            const int idx = tid + l * 128;
            const int arr = idx >> 8, rr = (idx >> 2) & 63, s = idx & 3;
            cp16(base + arr * R_AARR + rr * 80 + s * 16,
                 (arr ? aL : aH) + (long)rr * ldA + k0 + s * 8);
        }
        #pragma unroll
        for (int l = 0; l < 4; l++) {
            const int idx = tid + l * 128;
            const int arr = idx >> 8, rr = (idx >> 3) & 31, s = idx & 7;
            cp16(base + R_BOFF + arr * R_BARR + rr * 144 + s * 16,
                 (arr ? bL : bH) + (rowB + rr) * 512 + col0 + s * 8);
        }
        CPA_COMMIT();
    };

    load_chunk(0); load_chunk(1);
    for (int ch = 0; ch < 6; ch++) {
        if (ch + 2 < 6) load_chunk(ch + 2);
        if (ch < 4) asm volatile("cp.async.wait_group 2;" ::: "memory");
        else if (ch == 4) CPA_WAIT1();
        else CPA_WAIT0();
        __syncthreads();
        const uint32_t base = sb + (ch % 3) * R_BUF;
        #pragma unroll
        for (int ks = 0; ks < 2; ks++) {
            uint32_t ahf[2][4], alf[2][4], bb[2][4];
            #pragma unroll
            for (int mt = 0; mt < 2; mt++) {
                const uint32_t ra = base + (wm + mt * 16 + fRow) * 80 + (ks * 16 + fK) * 2;
                ldx4(ahf[mt], ra);
                ldx4(alf[mt], ra + R_AARR);
            }
            #pragma unroll
            for (int nt = 0; nt < 2; nt++) {
                const uint32_t rb = base + R_BOFF + (ks * 16 + tK) * 144 + (wn + nt * 16 + tN) * 2;
                ldx4t(bb[nt], rb);
            }
            #pragma unroll
            for (int mt = 0; mt < 2; mt++)
                #pragma unroll
                for (int nt = 0; nt < 2; nt++) {
                    mma16816(acc[mt][nt*2],   ahf[mt], bb[nt][0], bb[nt][1]);
                    mma16816(acc[mt][nt*2+1], ahf[mt], bb[nt][2], bb[nt][3]);
                    mma16816(acc[mt][nt*2],   alf[mt], bb[nt][0], bb[nt][1]);
                    mma16816(acc[mt][nt*2+1], alf[mt], bb[nt][2], bb[nt][3]);
                }
            #pragma unroll
            for (int nt = 0; nt < 2; nt++) {
                const uint32_t rb = base + R_BOFF + R_BARR + (ks * 16 + tK) * 144 + (wn + nt * 16 + tN) * 2;
                ldx4t(bb[nt], rb);
            }
            #pragma unroll
            for (int mt = 0; mt < 2; mt++)
                #pragma unroll
                for (int nt = 0; nt < 2; nt++) {
                    mma16816(acc[mt][nt*2],   ahf[mt], bb[nt][0], bb[nt][1]);
                    mma16816(acc[mt][nt*2+1], ahf[mt], bb[nt][2], bb[nt][3]);
                }
        }
        __syncthreads();
    }

    #pragma unroll
    for (int mt = 0; mt < 2; mt++)
        #pragma unroll
        for (int h = 0; h < 2; h++) {
            const int m = wm + mt * 16 + h * 8 + (lane >> 2);
            const int pos = (c & 15) * 64 + m;
            const float scale = rsqrtf((float)(pos + 1) * 64.0f);
            const long orow = ((long)c * 64 + m) * 512;
            #pragma unroll
            for (int n8 = 0; n8 < 4; n8++) {
                const int col = col0 + wn + n8 * 8 + (lane & 3) * 2;
                float2 o;
                o.x = acc[mt][n8][h*2+0] * scale;
                o.y = acc[mt][n8][h*2+1] * scale;
                *(float2*)&Out[orow + col] = o;
            }
        }
}

// ================= prep ====================================================
__global__ __launch_bounds__(256)
void prep_kernel(const float* __restrict__ x,
                 const float* __restrict__ W0, const float* __restrict__ W1,
                 const float* __restrict__ W2, const float* __restrict__ W3,
                 const float* __restrict__ Wk2, const float* __restrict__ Wq2,
                 bf16* __restrict__ xh, bf16* __restrict__ xl,
                 bf16* __restrict__ Wth, bf16* __restrict__ Wtl,
                 bf16* __restrict__ Wph, bf16* __restrict__ Wpl)
{
    const int bid = blockIdx.x, tid = threadIdx.x;
    if (bid < 1024) {
        const int i = bid * 256 + tid;
        float4 v = ((const float4*)x)[i];
        bsplit2(v.x, v.y, xh + i * 4,     xl + i * 4);
        bsplit2(v.z, v.w, xh + i * 4 + 2, xl + i * 4 + 2);
    } else if (bid < 2048) {
        const int widx = bid - 1024;
        const int z = widx >> 8, tile = widx & 255;
        const int k0 = (tile >> 4) * 32, n0 = (tile & 15) * 32;
        const float* W = z == 0 ? W0 : z == 1 ? W1 : z == 2 ? W2 : W3;
        __shared__ float t[32][33];
        #pragma unroll
        for (int j = 0; j < 4; j++) {
            const int r = (tid >> 5) + j * 8;
            t[r][tid & 31] = W[(long)(k0 + r) * 512 + n0 + (tid & 31)];
        }
        __syncthreads();
        #pragma unroll
        for (int j = 0; j < 4; j++) {
            const int nr = (tid >> 5) + j * 8, kc = tid & 31;
            const float v = t[kc][nr];
            const long o = (long)z * 262144 + (long)(n0 + nr) * 512 + k0 + kc;
            bf16 h = __float2bfloat16(v);
            Wth[o] = h;
            Wtl[o] = __float2bfloat16(v - __bfloat162float(h));
        }
    } else {
        const int widx = bid - 2048;
        const int z = widx >> 5, tile = widx & 31;
        const int k0 = (tile >> 1) * 32, n0 = (tile & 1) * 32;
        const float* W = z ? Wq2 : Wk2;
        __shared__ float t[32][33];
        #pragma unroll
        for (int j = 0; j < 4; j++) {
            const int r = (tid >> 5) + j * 8;
            t[r][tid & 31] = W[(long)(k0 + r) * 64 + n0 + (tid & 31)];
        }
        __syncthreads();
        #pragma unroll
        for (int j = 0; j < 4; j++) {
            const int nr = (tid >> 5) + j * 8, kc = tid & 31;
            const float v = t[kc][nr];
            const long o = (long)(z * 64 + n0 + nr) * 512 + k0 + kc;
            bf16 h = __float2bfloat16(v);
            Wph[o] = h;
            Wpl[o] = __float2bfloat16(v - __bfloat162float(h));
        }
    }
}

// ================= prefix ==================================================
__global__ __launch_bounds__(256)
void prefix_kernel(const float4* __restrict__ S, bf16* __restrict__ Ph,
                   bf16* __restrict__ Pl)
{
    GDS();
    int gidx = blockIdx.x * 256 + threadIdx.x;
    int b = gidx >> 14;
    int i = gidx & 16383;
    long base = (long)b * 16 * 16384 + i;
    float4 run = make_float4(0.f, 0.f, 0.f, 0.f);
    #pragma unroll
    for (int c = 0; c < 16; c++) {
        long idx = base + (long)c * 16384;
        long e = idx * 4;
        bsplit2(run.x, run.y, Ph + e,     Pl + e);
        bsplit2(run.z, run.w, Ph + e + 2, Pl + e + 2);
        float4 s = S[idx];
        run.x += s.x; run.y += s.y; run.z += s.z; run.w += s.w;
    }
}

// ================= LayerNorm (warp-per-row) ================================
__global__ __launch_bounds__(256)
void ln_kernel(const float* __restrict__ X, const float* __restrict__ gg,
               const float* __restrict__ bb, bf16* __restrict__ oh,
               bf16* __restrict__ ol)
{
    GDS();
    const int row = blockIdx.x * 8 + (threadIdx.x >> 5);
    const int lane = threadIdx.x & 31;
    const float4* Xr = (const float4*)(X + (long)row * 512);
    float4 v[4];
    float s = 0.f, sq = 0.f;
    #pragma unroll
    for (int q = 0; q < 4; q++) {
        v[q] = Xr[lane + 32 * q];
        s  += v[q].x + v[q].y + v[q].z + v[q].w;
        sq += v[q].x * v[q].x + v[q].y * v[q].y + v[q].z * v[q].z + v[q].w * v[q].w;
    }
    #pragma unroll
    for (int o = 16; o; o >>= 1) {
        s  += __shfl_xor_sync(0xFFFFFFFFu, s, o);
        sq += __shfl_xor_sync(0xFFFFFFFFu, sq, o);
    }
    const float mean = s * (1.0f / 512.0f);
    const float var  = sq * (1.0f / 512.0f) - mean * mean;
    const float rs   = rsqrtf(var + 1e-5f);
    #pragma unroll
    for (int q = 0; q < 4; q++) {
        const int idx = lane + 32 * q;
        float4 g4 = ((const float4*)gg)[idx];
        float4 b4 = ((const float4*)bb)[idx];
        float o0 = (v[q].x - mean) * rs * g4.x + b4.x;
        float o1 = (v[q].y - mean) * rs * g4.y + b4.y;
        float o2 = (v[q].z - mean) * rs * g4.z + b4.z;
        float o3 = (v[q].w - mean) * rs * g4.w + b4.w;
        long e = (long)row * 512 + idx * 4;
        bsplit2(o0, o1, oh + e,     ol + e);
        bsplit2(o2, o3, oh + e + 2, ol + e + 2);
    }
}

// ================= PDL launch helper =======================================
template<typename F, typename... Args>
static inline void pdl_launch(F* k, dim3 g, dim3 b, size_t sm, Args... a) {
    cudaLaunchConfig_t cfg = {};
    cfg.gridDim = g; cfg.blockDim = b; cfg.dynamicSmemBytes = sm; cfg.stream = 0;
    cudaLaunchAttribute at[1];
    at[0].id = cudaLaunchAttributeProgrammaticStreamSerialization;
    at[0].val.programmaticStreamSerializationAllowed = 1;
    cfg.attrs = at; cfg.numAttrs = 1;
    cudaLaunchKernelEx(&cfg, k, a...);
}

// ================= launch =================
extern "C" void kernel_launch(void* const* d_in, const int* in_sizes, int n_in,
                              void* d_out, int out_size)
{
    const float* x    = (const float*)d_in[0];
    const float* Wk1  = (const float*)d_in[1];
    const float* bk1  = (const float*)d_in[2];
    const float* Wk2  = (const float*)d_in[3];
    const float* bk2  = (const float*)d_in[4];
    const float* Wq1  = (const float*)d_in[5];
    const float* bq1  = (const float*)d_in[6];
    const float* Wq2  = (const float*)d_in[7];
    const float* bq2  = (const float*)d_in[8];
    const float* Wv   = (const float*)d_in[9];
    const float* bv   = (const float*)d_in[10];
    const float* ln_g = (const float*)d_in[11];
    const float* ln_b = (const float*)d_in[12];
    const float* Wo   = (const float*)d_in[13];
    const float* bo   = (const float*)d_in[14];
    float* out = (float*)d_out;

    void* p;
    cudaGetSymbolAddress(&p, g_xh);    bf16* xh    = (bf16*)p;
    cudaGetSymbolAddress(&p, g_xl);    bf16* xl    = (bf16*)p;
    cudaGetSymbolAddress(&p, g_Wth);   bf16* Wth   = (bf16*)p;
    cudaGetSymbolAddress(&p, g_Wtl);   bf16* Wtl   = (bf16*)p;
    cudaGetSymbolAddress(&p, g_Wph);   bf16* Wph   = (bf16*)p;
    cudaGetSymbolAddress(&p, g_Wpl);   bf16* Wpl   = (bf16*)p;
    cudaGetSymbolAddress(&p, g_Hkh);   bf16* Hkh   = (bf16*)p;
    cudaGetSymbolAddress(&p, g_Hkl);   bf16* Hkl   = (bf16*)p;
    cudaGetSymbolAddress(&p, g_Hqh);   bf16* Hqh   = (bf16*)p;
    cudaGetSymbolAddress(&p, g_Hql);   bf16* Hql   = (bf16*)p;
    cudaGetSymbolAddress(&p, g_Vh);    bf16* Vh    = (bf16*)p;
    cudaGetSymbolAddress(&p, g_Vl);    bf16* Vl    = (bf16*)p;
    cudaGetSymbolAddress(&p, g_CSkh);  bf16* CSkh  = (bf16*)p;
    cudaGetSymbolAddress(&p, g_CSkl);  bf16* CSkl  = (bf16*)p;
    cudaGetSymbolAddress(&p, g_CSqh);  bf16* CSqh  = (bf16*)p;
    cudaGetSymbolAddress(&p, g_CSql);  bf16* CSql  = (bf16*)p;
    cudaGetSymbolAddress(&p, g_CSkTh); bf16* CSkTh = (bf16*)p;
    cudaGetSymbolAddress(&p, g_CSkTl); bf16* CSkTl = (bf16*)p;
    cudaGetSymbolAddress(&p, g_Ach);   bf16* Ach   = (bf16*)p;
    cudaGetSymbolAddress(&p, g_Acl);   bf16* Acl   = (bf16*)p;
    cudaGetSymbolAddress(&p, g_S);     float* S    = (float*)p;
    cudaGetSymbolAddress(&p, g_Ph);    bf16* Ph    = (bf16*)p;
    cudaGetSymbolAddress(&p, g_Pl);    bf16* Pl    = (bf16*)p;
    cudaGetSymbolAddress(&p, g_R);     float* R    = (float*)p;
    cudaGetSymbolAddress(&p, g_LNh);   bf16* LNh   = (bf16*)p;
    cudaGetSymbolAddress(&p, g_LNl);   bf16* LNl   = (bf16*)p;

    static int attr_set = 0;
    if (!attr_set) {
        cudaFuncSetAttribute(mma_gemm<0>, cudaFuncAttributeMaxDynamicSharedMemorySize, X0_SMEM);
        cudaFuncSetAttribute(mma_gemm<1>, cudaFuncAttributeMaxDynamicSharedMemorySize, X1_SMEM);
        cudaFuncSetAttribute(phase_mma,   cudaFuncAttributeMaxDynamicSharedMemorySize, P_SMEM);
        cudaFuncSetAttribute(sac_mma,     cudaFuncAttributeMaxDynamicSharedMemorySize, SAC_SMEM);
        cudaFuncSetAttribute(r_mma,       cudaFuncAttributeMaxDynamicSharedMemorySize, R_SMEM);
        attr_set = 1;
    }

    // 0) conversions (plain launch)
    prep_kernel<<<2112, 256>>>(x, Wk1, Wq1, Wv, Wo, Wk2, Wq2,
                               xh, xl, Wth, Wtl, Wph, Wpl);

    // 1) XW: Hk(gelu), Hq(gelu), V(bias). grid (4,32,3)=384.
    pdl_launch(mma_gemm<0>, dim3(4,32,3), dim3(128), (size_t)X0_SMEM,
        (const bf16*)xh, (const bf16*)xl, (const bf16*)Wth, (const bf16*)Wtl,
        bk1, bq1, bv, (const float*)nullptr,
        Hkh, Hkl, Hqh, Hql, Vh, Vl, (float*)nullptr);

    // 2) Phases (split-K, 32-row tiles). grid (1,64,2)=128.
    pdl_launch(phase_mma, dim3(1,64,2), dim3(256), (size_t)P_SMEM,
        (const bf16*)Hkh, (const bf16*)Hkl, (const bf16*)Hqh, (const bf16*)Hql,
        (const bf16*)Wph, (const bf16*)Wpl, bk2, bq2,
        CSkh, CSkl, CSqh, CSql, CSkTh, CSkTl);

    // 3) S + Ac. grid (9,1,32)=288.
    pdl_launch(sac_mma, dim3(9,1,32), dim3(256), (size_t)SAC_SMEM,
        (const bf16*)CSkTh, (const bf16*)CSkTl, (const bf16*)Vh, (const bf16*)Vl,
        (const bf16*)CSqh, (const bf16*)CSql, (const bf16*)CSkh, (const bf16*)CSkl,
        S, Ach, Acl);

    // 4) exclusive prefix -> split bf16 P
    pdl_launch(prefix_kernel, dim3(128), dim3(256), (size_t)0,
        (const float4*)S, Ph, Pl);

    // 5) R. grid (8,1,32)=256.
    pdl_launch(r_mma, dim3(8,1,32), dim3(128), (size_t)R_SMEM,
        (const bf16*)CSqh, (const bf16*)CSql, (const bf16*)Ach, (const bf16*)Acl,
        (const bf16*)Ph, (const bf16*)Pl, (const bf16*)Vh, (const bf16*)Vl, R);

    // 6) LN -> split bf16 (warp-per-row)
    pdl_launch(ln_kernel, dim3(256), dim3(256), (size_t)0,
        (const float*)R, ln_g, ln_b, LNh, LNl);

    // 7) out = x + LN @ Wo + bo. grid (8,32)=256.
    pdl_launch(mma_gemm<1>, dim3(8,32,1), dim3(128), (size_t)X1_SMEM,
        (const bf16*)LNh, (const bf16*)LNl,
        (const bf16*)(Wth + 3L*262144), (const bf16*)(Wtl + 3L*262144),
        bo, (const float*)nullptr, (const float*)nullptr, (const float*)x,
        (bf16*)nullptr, (bf16*)nullptr, (bf16*)nullptr, (bf16*)nullptr,
        (bf16*)nullptr, (bf16*)nullptr, out);
}

// round 16
// speedup vs baseline: 1.0433x; 1.0142x over previous
#include <cuda_runtime.h>
#include <cuda_bf16.h>
#include <math.h>
#include <stdint.h>

#define PI_F 3.14159265358979323846f
typedef __nv_bfloat16 bf16;

// PDL: wait for upstream kernel's data before consuming (sm_90+)
#define GDS() asm volatile("griddepcontrol.wait;" ::: "memory")

// ---------------- scratch ----------------
__device__ bf16 g_xh  [2048 * 512];
__device__ bf16 g_xl  [2048 * 512];
__device__ bf16 g_Wth [4 * 512 * 512];
__device__ bf16 g_Wtl [4 * 512 * 512];
__device__ bf16 g_Wph [128 * 512];
__device__ bf16 g_Wpl [128 * 512];
__device__ bf16 g_Hkh [2048 * 512];
__device__ bf16 g_Hkl [2048 * 512];
__device__ bf16 g_Hqh [2048 * 512];
__device__ bf16 g_Hql [2048 * 512];
__device__ bf16 g_Vh  [2048 * 512];
__device__ bf16 g_Vl  [2048 * 512];
__device__ bf16 g_CSkh[2048 * 128];
__device__ bf16 g_CSkl[2048 * 128];
__device__ bf16 g_CSqh[2048 * 128];
__device__ bf16 g_CSql[2048 * 128];
__device__ bf16 g_CSkTh[32 * 128 * 64];
__device__ bf16 g_CSkTl[32 * 128 * 64];
__device__ bf16 g_Ach [32 * 64 * 64];
__device__ bf16 g_Acl [32 * 64 * 64];
__device__ float g_S  [32 * 128 * 512];
__device__ bf16 g_Ph  [32 * 128 * 512];
__device__ bf16 g_Pl  [32 * 128 * 512];
__device__ float g_R  [2048 * 512];
__device__ bf16 g_LNh [2048 * 512];
__device__ bf16 g_LNl [2048 * 512];

// ================= PTX helpers =================
__device__ __forceinline__ uint32_t smem_u32(const void* p) {
    uint32_t a;
    asm("{ .reg .u64 t; cvta.to.shared.u64 t, %1; cvt.u32.u64 %0, t; }" : "=r"(a) : "l"(p));
    return a;
}
__device__ __forceinline__ void cp16(uint32_t dst, const void* src) {
    asm volatile("cp.async.cg.shared.global [%0], [%1], 16;" :: "r"(dst), "l"(src));
}
__device__ __forceinline__ void ldx4(uint32_t* r, uint32_t addr) {
    asm volatile("ldmatrix.sync.aligned.m8n8.x4.shared.b16 {%0,%1,%2,%3}, [%4];"
        : "=r"(r[0]), "=r"(r[1]), "=r"(r[2]), "=r"(r[3]) : "r"(addr));
}
__device__ __forceinline__ void ldx4t(uint32_t* r, uint32_t addr) {
    asm volatile("ldmatrix.sync.aligned.m8n8.x4.trans.shared.b16 {%0,%1,%2,%3}, [%4];"
        : "=r"(r[0]), "=r"(r[1]), "=r"(r[2]), "=r"(r[3]) : "r"(addr));
}
__device__ __forceinline__ void mma16816(float* c, const uint32_t* a,
                                         uint32_t b0, uint32_t b1) {
    asm volatile("mma.sync.aligned.m16n8k16.row.col.f32.bf16.bf16.f32 "
        "{%0,%1,%2,%3}, {%4,%5,%6,%7}, {%8,%9}, {%0,%1,%2,%3};"
        : "+f"(c[0]), "+f"(c[1]), "+f"(c[2]), "+f"(c[3])
        : "r"(a[0]), "r"(a[1]), "r"(a[2]), "r"(a[3]), "r"(b0), "r"(b1));
}
__device__ __forceinline__ void bsplit2(float v0, float v1, bf16* hd, bf16* ld) {
    __nv_bfloat162 h, l;
    h.x = __float2bfloat16(v0); h.y = __float2bfloat16(v1);
    l.x = __float2bfloat16(v0 - __bfloat162float(h.x));
    l.y = __float2bfloat16(v1 - __bfloat162float(h.y));
    *(__nv_bfloat162*)hd = h; *(__nv_bfloat162*)ld = l;
}
#define CPA_COMMIT() asm volatile("cp.async.commit_group;" ::: "memory")
#define CPA_WAIT1()  asm volatile("cp.async.wait_group 1;" ::: "memory")
#define CPA_WAIT0()  asm volatile("cp.async.wait_group 0;" ::: "memory")

// ================= XW / OUT GEMM: 64xBN tile, 128 thr, 4 warps (2m x 2n) ====
static constexpr int XA_ARR = 64 * 80;
static constexpr int XB_OFF = 2 * XA_ARR;
static constexpr int X0_SMEM = 2 * (XB_OFF + 2 * 128 * 80);  // 61440
static constexpr int X1_SMEM = 2 * (XB_OFF + 2 * 64 * 80);   // 40960

template<int MODE>   // 0: BN=128 XW (split bf16 out, gelu z<2); 1: BN=64 fp32+resid
__global__ __launch_bounds__(128, 3)
void mma_gemm(const bf16* __restrict__ Ah, const bf16* __restrict__ Al,
              const bf16* __restrict__ Wth, const bf16* __restrict__ Wtl,
              const float* __restrict__ b0, const float* __restrict__ b1,
              const float* __restrict__ b2, const float* __restrict__ resid,
              bf16* __restrict__ O0h, bf16* __restrict__ O0l,
              bf16* __restrict__ O1h, bf16* __restrict__ O1l,
              bf16* __restrict__ O2h, bf16* __restrict__ O2l,
              float* __restrict__ Cout)
{
    constexpr int BN = (MODE == 0) ? 128 : 64;
    constexpr int NT = BN / 32;
    constexpr int XB_ARR = BN * 80;
    constexpr int X_BUF  = XB_OFF + 2 * XB_ARR;
    constexpr int BLD = BN / 16;

    GDS();
    extern __shared__ __align__(128) char smem[];
    const uint32_t sb = smem_u32(smem);
    const int tid = threadIdx.x, wid = tid >> 5, lane = tid & 31;
    const int row0 = blockIdx.y * 64, col0 = blockIdx.x * BN;
    const int z = (MODE == 0) ? (int)blockIdx.z : 0;
    const bf16* Bh = Wth + (long)z * 262144;
    const bf16* Bl = Wtl + (long)z * 262144;
    const float* bias = (z == 0) ? b0 : (z == 1 ? b1 : b2);
    const bool gelu = (MODE == 0) && (z < 2);
    bf16* Oh = (z == 0) ? O0h : (z == 1 ? O1h : O2h);
    bf16* Ol = (z == 0) ? O0l : (z == 1 ? O1l : O2l);

    const int wm = (wid & 1) * 32, wn = (wid >> 1) * (BN / 2);
    float acc[2][2 * NT][4];
    #pragma unroll
    for (int i = 0; i < 2; i++)
        #pragma unroll
        for (int j = 0; j < 2 * NT; j++)
            #pragma unroll
            for (int e = 0; e < 4; e++) acc[i][j][e] = 0.0f;

    const int g = lane >> 3, wr = lane & 7;
    const int fRow = wr + (g & 1) * 8, fK = (g >> 1) * 8;

    auto load_chunk = [&](int ch, int b) {
        const int k0 = ch * 32;
        const uint32_t base = sb + b * X_BUF;
        #pragma unroll
        for (int l = 0; l < 4; l++) {
            const int idx = tid + l * 128;
            const int arr = idx >> 8, rr = (idx >> 2) & 63, s = idx & 3;
            cp16(base + arr * XA_ARR + rr * 80 + s * 16,
                 (arr ? Al : Ah) + (long)(row0 + rr) * 512 + k0 + s * 8);
        }
        #pragma unroll
        for (int l = 0; l < BLD; l++) {
            const int idx = tid + l * 128;
            const int arr = idx / (BN * 4), rr = (idx >> 2) % BN, s = idx & 3;
            cp16(base + XB_OFF + arr * XB_ARR + rr * 80 + s * 16,
                 (arr ? Bl : Bh) + (long)(col0 + rr) * 512 + k0 + s * 8);
        }
        CPA_COMMIT();
    };

    load_chunk(0, 0);
    for (int ch = 0; ch < 16; ch++) {
        const int b = ch & 1;
        if (ch < 15) { load_chunk(ch + 1, b ^ 1); CPA_WAIT1(); }
        else CPA_WAIT0();
        __syncthreads();
        const uint32_t base = sb + b * X_BUF;
        #pragma unroll
        for (int ks = 0; ks < 2; ks++) {
            uint32_t ahf[2][4], alf[2][4], bb[NT][4];
            #pragma unroll
            for (int mt = 0; mt < 2; mt++) {
                const uint32_t ra = base + (wm + mt * 16 + fRow) * 80 + (ks * 16 + fK) * 2;
                ldx4(ahf[mt], ra);
                ldx4(alf[mt], ra + XA_ARR);
            }
            #pragma unroll
            for (int nt = 0; nt < NT; nt++) {
                const uint32_t rb = base + XB_OFF + (wn + nt * 16 + fRow) * 80 + (ks * 16 + fK) * 2;
                ldx4(bb[nt], rb);
            }
            #pragma unroll
            for (int mt = 0; mt < 2; mt++)
                #pragma unroll
                for (int nt = 0; nt < NT; nt++) {
                    mma16816(acc[mt][nt*2],   ahf[mt], bb[nt][0], bb[nt][2]);
                    mma16816(acc[mt][nt*2+1], ahf[mt], bb[nt][1], bb[nt][3]);
                    mma16816(acc[mt][nt*2],   alf[mt], bb[nt][0], bb[nt][2]);
                    mma16816(acc[mt][nt*2+1], alf[mt], bb[nt][1], bb[nt][3]);
                }
            #pragma unroll
            for (int nt = 0; nt < NT; nt++) {
                const uint32_t rb = base + XB_OFF + XB_ARR + (wn + nt * 16 + fRow) * 80 + (ks * 16 + fK) * 2;
                ldx4(bb[nt], rb);
            }
            #pragma unroll
            for (int mt = 0; mt < 2; mt++)
                #pragma unroll
                for (int nt = 0; nt < NT; nt++) {
                    mma16816(acc[mt][nt*2],   ahf[mt], bb[nt][0], bb[nt][2]);
                    mma16816(acc[mt][nt*2+1], ahf[mt], bb[nt][1], bb[nt][3]);
                }
        }
        __syncthreads();
    }

    #pragma unroll
    for (int mt = 0; mt < 2; mt++)
        #pragma unroll
        for (int h = 0; h < 2; h++) {
            const int row = row0 + wm + mt * 16 + h * 8 + (lane >> 2);
            #pragma unroll
            for (int n8 = 0; n8 < 2 * NT; n8++) {
                const int col = col0 + wn + n8 * 8 + (lane & 3) * 2;
                float v0 = acc[mt][n8][h * 2 + 0];
                float v1 = acc[mt][n8][h * 2 + 1];
                const float2 bq = *(const float2*)&bias[col];
                v0 += bq.x; v1 += bq.y;
                if (MODE == 0) {
                    if (gelu) {
                        v0 = 0.5f * v0 * (1.0f + erff(v0 * 0.70710678118654752f));
                        v1 = 0.5f * v1 * (1.0f + erff(v1 * 0.70710678118654752f));
                    }
                    bsplit2(v0, v1, Oh + (long)row * 512 + col, Ol + (long)row * 512 + col);
                } else {
                    const float2 r2 = *(const float2*)&resid[(long)row * 512 + col];
                    float2 o; o.x = v0 + r2.x; o.y = v1 + r2.y;
                    *(float2*)&Cout[(long)row * 512 + col] = o;
                }
            }
        }
}

// ================= phase GEMM: 32x64 tile, 256 thr, split-K (2 groups) =====
static constexpr int PH_A    = 32 * 80;
static constexpr int PH_HALF = 2 * PH_A + 2 * 64 * 80;
static constexpr int PH_STG  = 2 * PH_HALF;
static constexpr int P_SMEM  = 2 * PH_STG;   // 61440

__global__ __launch_bounds__(256)
void phase_mma(const bf16* __restrict__ Hkh, const bf16* __restrict__ Hkl,
               const bf16* __restrict__ Hqh, const bf16* __restrict__ Hql,
               const bf16* __restrict__ Wph, const bf16* __restrict__ Wpl,
               const float* __restrict__ bk2, const float* __restrict__ bq2,
               bf16* __restrict__ CSkh, bf16* __restrict__ CSkl,
               bf16* __restrict__ CSqh, bf16* __restrict__ CSql,
               bf16* __restrict__ CSkTh, bf16* __restrict__ CSkTl)
{
    GDS();
    extern __shared__ __align__(128) char smem[];
    const uint32_t sb = smem_u32(smem);
    const int tid = threadIdx.x, wid = tid >> 5, lane = tid & 31;
    const int z = blockIdx.z, row0 = blockIdx.y * 32;
    const bf16* Ah = z ? Hqh : Hkh;
    const bf16* Al = z ? Hql : Hkl;
    const bf16* Bh = Wph + (long)z * 64 * 512;
    const bf16* Bl = Wpl + (long)z * 64 * 512;
    const float* bias = z ? bq2 : bk2;

    const int grp = wid >> 2;
    const int wid2 = wid & 3;
    const int wm = (wid2 & 1) * 16, wn = (wid2 >> 1) * 32;
    float acc[4][4];
    #pragma unroll
    for (int j = 0; j < 4; j++)
        #pragma unroll
        for (int e = 0; e < 4; e++) acc[j][e] = 0.0f;

    const int g = lane >> 3, wr = lane & 7;
    const int fRow = wr + (g & 1) * 8, fK = (g >> 1) * 8;

    auto load_chunk = [&](int ch) {
        const int k0 = ch * 32;
        const uint32_t base = sb + (ch & 1) * PH_STG;
        #pragma unroll
        for (int l = 0; l < 2; l++) {
            const int idx = tid + l * 256;
            const int hf = idx >> 8, ii = idx & 255;
            const int arr = ii >> 7, pos = ii & 127, rr = pos >> 2, s = pos & 3;
            cp16(base + hf * PH_HALF + arr * PH_A + rr * 80 + s * 16,
                 (arr ? Al : Ah) + (long)(row0 + rr) * 512 + hf * 256 + k0 + s * 8);
        }
        #pragma unroll
        for (int l = 0; l < 4; l++) {
            const int idx = tid + l * 256;
            const int hf = idx >> 9, ii = idx & 511;
            const int arr = ii >> 8, pos = ii & 255, rr = pos >> 2, s = pos & 3;
            cp16(base + hf * PH_HALF + 2 * PH_A + arr * 5120 + rr * 80 + s * 16,
                 (arr ? Bl : Bh) + (long)rr * 512 + hf * 256 + k0 + s * 8);
        }
        CPA_COMMIT();
    };

    load_chunk(0);
    for (int ch = 0; ch < 8; ch++) {
        if (ch < 7) { load_chunk(ch + 1); CPA_WAIT1(); }
        else CPA_WAIT0();
        __syncthreads();
        const uint32_t hbase = sb + (ch & 1) * PH_STG + grp * PH_HALF;
        #pragma unroll
        for (int ks = 0; ks < 2; ks++) {
            uint32_t ahf[4], alf[4], bb[2][4];
            {
                const uint32_t ra = hbase + (wm + fRow) * 80 + (ks * 16 + fK) * 2;
                ldx4(ahf, ra);
                ldx4(alf, ra + PH_A);
            }
            #pragma unroll
            for (int nt = 0; nt < 2; nt++) {
                const uint32_t rb = hbase + 2 * PH_A + (wn + nt * 16 + fRow) * 80 + (ks * 16 + fK) * 2;
                ldx4(bb[nt], rb);
            }
            #pragma unroll
            for (int nt = 0; nt < 2; nt++) {
                mma16816(acc[nt*2],   ahf, bb[nt][0], bb[nt][2]);
                mma16816(acc[nt*2+1], ahf, bb[nt][1], bb[nt][3]);
                mma16816(acc[nt*2],   alf, bb[nt][0], bb[nt][2]);
                mma16816(acc[nt*2+1], alf, bb[nt][1], bb[nt][3]);
            }
            #pragma unroll
            for (int nt = 0; nt < 2; nt++) {
                const uint32_t rb = hbase + 2 * PH_A + 5120 + (wn + nt * 16 + fRow) * 80 + (ks * 16 + fK) * 2;
                ldx4(bb[nt], rb);
            }
            #pragma unroll
            for (int nt = 0; nt < 2; nt++) {
                mma16816(acc[nt*2],   ahf, bb[nt][0], bb[nt][2]);
                mma16816(acc[nt*2+1], ahf, bb[nt][1], bb[nt][3]);
            }
        }
        __syncthreads();
    }

    float* red = (float*)smem;
    #pragma unroll
    for (int j = 0; j < 4; j++)
        *(float4*)&red[tid * 16 + j * 4] = *(float4*)acc[j];
    __syncthreads();
    if (tid < 128) {
        #pragma unroll
        for (int j = 0; j < 4; j++) {
            float4 o = *(float4*)&red[(tid + 128) * 16 + j * 4];
            acc[j][0] += o.x; acc[j][1] += o.y; acc[j][2] += o.z; acc[j][3] += o.w;
        }
        #pragma unroll
        for (int h = 0; h < 2; h++) {
            const int row = row0 + wm + h * 8 + (lane >> 2);
            #pragma unroll
            for (int j = 0; j < 4; j++) {
                const int n = wn + (j >> 1) * 16 + (j & 1) * 8 + (lane & 3) * 2;
                float v0 = acc[j][h * 2 + 0] + bias[n];
                float v1 = acc[j][h * 2 + 1] + bias[n + 1];
                float p0 = tanhf(v0) * PI_F, p1 = tanhf(v1) * PI_F;
                float c0, s0, c1, s1;
                sincosf(p0, &s0, &c0);
                sincosf(p1, &s1, &c1);
                bf16* Rh = z ? CSqh : CSkh;
                bf16* Rl = z ? CSql : CSkl;
                const long rb_ = (long)row * 128;
                bsplit2(c0, c1, Rh + rb_ + n,      Rl + rb_ + n);
                bsplit2(s0, s1, Rh + rb_ + n + 64, Rl + rb_ + n + 64);
                if (!z) {
                    const int c = row >> 6, ro = row & 63;
                    const long t0 = (long)c * 8192 + (long)n * 64 + ro;
                    bf16 h0 = __float2bfloat16(c0);
                    bf16 h1 = __float2bfloat16(c1);
                    bf16 h2 = __float2bfloat16(s0);
                    bf16 h3 = __float2bfloat16(s1);
                    CSkTh[t0]        = h0;
                    CSkTh[t0 + 64]   = h1;
                    CSkTh[t0 + 4096] = h2;
                    CSkTh[t0 + 4160] = h3;
                    CSkTl[t0]        = __float2bfloat16(c0 - __bfloat162float(h0));
                    CSkTl[t0 + 64]   = __float2bfloat16(c1 - __bfloat162float(h1));
                    CSkTl[t0 + 4096] = __float2bfloat16(s0 - __bfloat162float(h2));
                    CSkTl[t0 + 4160] = __float2bfloat16(s1 - __bfloat162float(h3));
                }
            }
        }
    }
}

// ================= S + Ac combined launch ==================================
static constexpr int S_AARR = 128 * 80;
static constexpr int S_BOFF = 2 * S_AARR;
static constexpr int S_BARR = 32 * 144;
static constexpr int S_BUF  = S_BOFF + 2 * S_BARR;
static constexpr int SAC_SMEM = 2 * S_BUF;
static constexpr int AC_AARR = 64 * 80;
static constexpr int AC_BOFF = 2 * AC_AARR;
static constexpr int AC_BUF  = 2 * AC_BOFF;

__global__ __launch_bounds__(256)
void sac_mma(const bf16* __restrict__ CSkTh, const bf16* __restrict__ CSkTl,
             const bf16* __restrict__ Vh, const bf16* __restrict__ Vl,
             const bf16* __restrict__ CSqh, const bf16* __restrict__ CSql,
             const bf16* __restrict__ CSkh, const bf16* __restrict__ CSkl,
             float* __restrict__ S, bf16* __restrict__ Ach, bf16* __restrict__ Acl)
{
    GDS();
    extern __shared__ __align__(128) char smem[];
    const uint32_t sb = smem_u32(smem);
    const int tid = threadIdx.x, wid = tid >> 5, lane = tid & 31;
    const int c = blockIdx.z;
    const int g = lane >> 3, wr = lane & 7;
    const int fRow = wr + (g & 1) * 8, fK = (g >> 1) * 8;
    const int tK = fRow, tN = (g >> 1) * 8;

    if (blockIdx.x < 8) {
        const int col0 = blockIdx.x * 64;
        const int wm = (wid & 3) * 32, wn = (wid >> 2) * 32;
        float acc[2][4][4];
        #pragma unroll
        for (int i = 0; i < 2; i++)
            #pragma unroll
            for (int j = 0; j < 4; j++)
                #pragma unroll
                for (int e = 0; e < 4; e++) acc[i][j][e] = 0.0f;

        auto load_chunk = [&](int ch, int b) {
            const int k0 = ch * 32;
            const uint32_t base = sb + b * S_BUF;
            #pragma unroll
            for (int l = 0; l < 4; l++) {
                const int idx = tid + l * 256;
                const int arr = idx >> 9, rr = (idx >> 2) & 127, s = idx & 3;
                cp16(base + arr * S_AARR + rr * 80 + s * 16,
                     (arr ? CSkTl : CSkTh) + (long)c * 8192 + (long)rr * 64 + k0 + s * 8);
            }
            #pragma unroll
            for (int l = 0; l < 2; l++) {
                const int idx = tid + l * 256;
                const int arr = idx >> 8, rr = (idx >> 3) & 31, s = idx & 7;
                cp16(base + S_BOFF + arr * S_BARR + rr * 144 + s * 16,
                     (arr ? Vl : Vh) + ((long)c * 64 + k0 + rr) * 512 + col0 + s * 8);
            }
            CPA_COMMIT();
        };

        load_chunk(0, 0);
        load_chunk(1, 1);
        for (int ch = 0; ch < 2; ch++) {
            if (ch == 0) CPA_WAIT1(); else CPA_WAIT0();
            __syncthreads();
            const uint32_t base = sb + ch * S_BUF;
            #pragma unroll
            for (int ks = 0; ks < 2; ks++) {
                uint32_t ahf[2][4], alf[2][4], bb[2][4];
                #pragma unroll
                for (int mt = 0; mt < 2; mt++) {
                    const uint32_t ra = base + (wm + mt * 16 + fRow) * 80 + (ks * 16 + fK) * 2;
                    ldx4(ahf[mt], ra);
                    ldx4(alf[mt], ra + S_AARR);
                }
                #pragma unroll
                for (int nt = 0; nt < 2; nt++) {
                    const uint32_t rb = base + S_BOFF + (ks * 16 + tK) * 144 + (wn + nt * 16 + tN) * 2;
                    ldx4t(bb[nt], rb);
                }
                #pragma unroll
                for (int mt = 0; mt < 2; mt++)
                    #pragma unroll
                    for (int nt = 0; nt < 2; nt++) {
                        mma16816(acc[mt][nt*2],   ahf[mt], bb[nt][0], bb[nt][1]);
                        mma16816(acc[mt][nt*2+1], ahf[mt], bb[nt][2], bb[nt][3]);
                        mma16816(acc[mt][nt*2],   alf[mt], bb[nt][0], bb[nt][1]);
                        mma16816(acc[mt][nt*2+1], alf[mt], bb[nt][2], bb[nt][3]);
                    }
                #pragma unroll
                for (int nt = 0; nt < 2; nt++) {
                    const uint32_t rb = base + S_BOFF + S_BARR + (ks * 16 + tK) * 144 + (wn + nt * 16 + tN) * 2;
                    ldx4t(bb[nt], rb);
                }
                #pragma unroll
                for (int mt = 0; mt < 2; mt++)
                    #pragma unroll
                    for (int nt = 0; nt < 2; nt++) {
                        mma16816(acc[mt][nt*2],   ahf[mt], bb[nt][0], bb[nt][1]);
                        mma16816(acc[mt][nt*2+1], ahf[mt], bb[nt][2], bb[nt][3]);
                    }
            }
            __syncthreads();
        }

        #pragma unroll
        for (int mt = 0; mt < 2; mt++)
            #pragma unroll
            for (int h = 0; h < 2; h++) {
                const int m = wm + mt * 16 + h * 8 + (lane >> 2);
                const long orow = (long)c * 65536 + (long)m * 512;
                #pragma unroll
                for (int n8 = 0; n8 < 4; n8++) {
                    const int col = col0 + wn + n8 * 8 + (lane & 3) * 2;
                    float2 o; o.x = acc[mt][n8][h*2+0]; o.y = acc[mt][n8][h*2+1];
                    *(float2*)&S[orow + col] = o;
                }
            }
    } else {
        const int wm = (wid & 1) * 32, wn = (wid >> 1) * 16;
        float acc[2][2][4];
        #pragma unroll
        for (int i = 0; i < 2; i++)
            #pragma unroll
            for (int j = 0; j < 2; j++)
                #pragma unroll
                for (int e = 0; e < 4; e++) acc[i][j][e] = 0.0f;

        auto load_chunk = [&](int ch, int b) {
            const int k0 = ch * 32;
            const uint32_t base = sb + b * AC_BUF;
            #pragma unroll
            for (int l = 0; l < 2; l++) {
                const int idx = tid + l * 256;
                const int arr = idx >> 8, rr = (idx >> 2) & 63, s = idx & 3;
                cp16(base + arr * AC_AARR + rr * 80 + s * 16,
                     (arr ? CSql : CSqh) + ((long)c * 64 + rr) * 128 + k0 + s * 8);
            }
            #pragma unroll
            for (int l = 0; l < 2; l++) {
                const int idx = tid + l * 256;
                const int arr = idx >> 8, rr = (idx >> 2) & 63, s = idx & 3;
                cp16(base + AC_BOFF + arr * AC_AARR + rr * 80 + s * 16,
                     (arr ? CSkl : CSkh) + ((long)c * 64 + rr) * 128 + k0 + s * 8);
            }
            CPA_COMMIT();
        };

        load_chunk(0, 0);
        for (int ch = 0; ch < 4; ch++) {
            const int b = ch & 1;
            if (ch < 3) { load_chunk(ch + 1, b ^ 1); CPA_WAIT1(); }
            else CPA_WAIT0();
            __syncthreads();
            const uint32_t base = sb + b * AC_BUF;
            #pragma unroll
            for (int ks = 0; ks < 2; ks++) {
                uint32_t ahf[2][4], alf[2][4], bb[4];
                #pragma unroll
                for (int mt = 0; mt < 2; mt++) {
                    const uint32_t ra = base + (wm + mt * 16 + fRow) * 80 + (ks * 16 + fK) * 2;
                    ldx4(ahf[mt], ra);
                    ldx4(alf[mt], ra + AC_AARR);
                }
                {
                    const uint32_t rb = base + AC_BOFF + (wn + fRow) * 80 + (ks * 16 + fK) * 2;
                    ldx4(bb, rb);
                }
                #pragma unroll
                for (int mt = 0; mt < 2; mt++) {
                    mma16816(acc[mt][0], ahf[mt], bb[0], bb[2]);
                    mma16816(acc[mt][1], ahf[mt], bb[1], bb[3]);
                    mma16816(acc[mt][0], alf[mt], bb[0], bb[2]);
                    mma16816(acc[mt][1], alf[mt], bb[1], bb[3]);
                }
                {
                    const uint32_t rb = base + AC_BOFF + AC_AARR + (wn + fRow) * 80 + (ks * 16 + fK) * 2;
                    ldx4(bb, rb);
                }
                #pragma unroll
                for (int mt = 0; mt < 2; mt++) {
                    mma16816(acc[mt][0], ahf[mt], bb[0], bb[2]);
                    mma16816(acc[mt][1], ahf[mt], bb[1], bb[3]);
                }
            }
            __syncthreads();
        }

        #pragma unroll
        for (int mt = 0; mt < 2; mt++)
            #pragma unroll
            for (int h = 0; h < 2; h++) {
                const int row = wm + mt * 16 + h * 8 + (lane >> 2);
                #pragma unroll
                for (int n8 = 0; n8 < 2; n8++) {
                    const int col = wn + n8 * 8 + (lane & 3) * 2;
                    float v0 = (col     <= row) ? acc[mt][n8][h*2+0] : 0.0f;
                    float v1 = (col + 1 <= row) ? acc[mt][n8][h*2+1] : 0.0f;
                    const long o = (long)c * 4096 + (long)row * 64 + col;
                    bsplit2(v0, v1, Ach + o, Acl + o);
                }
            }
    }
}

// ================= R GEMM: M64,N64,K192, 128 thr ===========================
static constexpr int R_AARR = 64 * 80;
static constexpr int R_BOFF = 2 * R_AARR;
static constexpr int R_BARR = 32 * 144;
static constexpr int R_BUF  = R_BOFF + 2 * R_BARR;
static constexpr int R_SMEM = 3 * R_BUF;

__global__ __launch_bounds__(128)
void r_mma(const bf16* __restrict__ CSqh, const bf16* __restrict__ CSql,
           const bf16* __restrict__ Ach, const bf16* __restrict__ Acl,
           const bf16* __restrict__ Ph, const bf16* __restrict__ Pl,
           const bf16* __restrict__ Vh, const bf16* __restrict__ Vl,
           float* __restrict__ Out)
{
    GDS();
    extern __shared__ __align__(128) char smem[];
    const uint32_t sb = smem_u32(smem);
    const int tid = threadIdx.x, wid = tid >> 5, lane = tid & 31;
    const int c = blockIdx.z, col0 = blockIdx.x * 64;
    const int wm = (wid & 1) * 32, wn = (wid >> 1) * 32;
    const int g = lane >> 3, wr = lane & 7;
    const int fRow = wr + (g & 1) * 8, fK = (g >> 1) * 8;
    const int tK = fRow, tN = (g >> 1) * 8;

    float acc[2][4][4];
    #pragma unroll
    for (int i = 0; i < 2; i++)
        #pragma unroll
        for (int j = 0; j < 4; j++)
            #pragma unroll
            for (int e = 0; e < 4; e++) acc[i][j][e] = 0.0f;

    auto load_chunk = [&](int ch) {
        const uint32_t base = sb + (ch % 3) * R_BUF;
        const bf16 *aH, *aL, *bH, *bL;
        int ldA, k0;
        long rowB;
        if (ch < 4) {
            aH = CSqh + (long)c * 8192; aL = CSql + (long)c * 8192;
            ldA = 128; k0 = ch * 32;
            bH = Ph; bL = Pl; rowB = (long)c * 128 + ch * 32;
        } else {
            aH = Ach + (long)c * 4096; aL = Acl + (long)c * 4096;
            ldA = 64; k0 = (ch - 4) * 32;
            bH = Vh; bL = Vl; rowB = (long)c * 64 + (ch - 4) * 32;
        }
        #pragma unroll
        for (int l = 0; l < 4; l++) {
            const int idx = tid + l * 128;
            const int arr = idx >> 8, rr = (idx >> 2) & 63, s = idx & 3;
            cp16(base + arr * R_AARR + rr * 80 + s * 16,
                 (arr ? aL : aH) + (long)rr * ldA + k0 + s * 8);
        }
        #pragma unroll
        for (int l = 0; l < 4; l++) {
            const int idx = tid + l * 128;
            const int arr = idx >> 8, rr = (idx >> 3) & 31, s = idx & 7;
            cp16(base + R_BOFF + arr * R_BARR + rr * 144 + s * 16,
                 (arr ? bL : bH) + (rowB + rr) * 512 + col0 + s * 8);
        }
        CPA_COMMIT();
    };

    load_chunk(0); load_chunk(1);
    for (int ch = 0; ch < 6; ch++) {
        if (ch + 2 < 6) load_chunk(ch + 2);
        if (ch < 4) asm volatile("cp.async.wait_group 2;" ::: "memory");
        else if (ch == 4) CPA_WAIT1();
        else CPA_WAIT0();
        __syncthreads();
        const uint32_t base = sb + (ch % 3) * R_BUF;
        #pragma unroll
        for (int ks = 0; ks < 2; ks++) {
            uint32_t ahf[2][4], alf[2][4], bb[2][4];
            #pragma unroll
            for (int mt = 0; mt < 2; mt++) {
                const uint32_t ra = base + (wm + mt * 16 + fRow) * 80 + (ks * 16 + fK) * 2;
                ldx4(ahf[mt], ra);
                ldx4(alf[mt], ra + R_AARR);
            }
            #pragma unroll
            for (int nt = 0; nt < 2; nt++) {
                const uint32_t rb = base + R_BOFF + (ks * 16 + tK) * 144 + (wn + nt * 16 + tN) * 2;
                ldx4t(bb[nt], rb);
            }
            #pragma unroll
            for (int mt = 0; mt < 2; mt++)
                #pragma unroll
                for (int nt = 0; nt < 2; nt++) {
                    mma16816(acc[mt][nt*2],   ahf[mt], bb[nt][0], bb[nt][1]);
                    mma16816(acc[mt][nt*2+1], ahf[mt], bb[nt][2], bb[nt][3]);
                    mma16816(acc[mt][nt*2],   alf[mt], bb[nt][0], bb[nt][1]);
                    mma16816(acc[mt][nt*2+1], alf[mt], bb[nt][2], bb[nt][3]);
                }
            #pragma unroll
            for (int nt = 0; nt < 2; nt++) {
                const uint32_t rb = base + R_BOFF + R_BARR + (ks * 16 + tK) * 144 + (wn + nt * 16 + tN) * 2;
                ldx4t(bb[nt], rb);
            }
            #pragma unroll
            for (int mt = 0; mt < 2; mt++)
                #pragma unroll
                for (int nt = 0; nt < 2; nt++) {
                    mma16816(acc[mt][nt*2],   ahf[mt], bb[nt][0], bb[nt][1]);
                    mma16816(acc[mt][nt*2+1], ahf[mt], bb[nt][2], bb[nt][3]);
                }
        }
        __syncthreads();
    }

    #pragma unroll
    for (int mt = 0; mt < 2; mt++)
        #pragma unroll
        for (int h = 0; h < 2; h++) {
            const int m = wm + mt * 16 + h * 8 + (lane >> 2);
            const int pos = (c & 15) * 64 + m;
            const float scale = rsqrtf((float)(pos + 1) * 64.0f);
            const long orow = ((long)c * 64 + m) * 512;
            #pragma unroll
            for (int n8 = 0; n8 < 4; n8++) {
                const int col = col0 + wn + n8 * 8 + (lane & 3) * 2;
                float2 o;
                o.x = acc[mt][n8][h*2+0] * scale;
                o.y = acc[mt][n8][h*2+1] * scale;
                *(float2*)&Out[orow + col] = o;
            }
        }
}

// ================= prep ====================================================
__global__ __launch_bounds__(256)
void prep_kernel(const float* __restrict__ x,
                 const float* __restrict__ W0, const float* __restrict__ W1,
                 const float* __restrict__ W2, const float* __restrict__ W3,
                 const float* __restrict__ Wk2, const float* __restrict__ Wq2,
                 bf16* __restrict__ xh, bf16* __restrict__ xl,
                 bf16* __restrict__ Wth, bf16* __restrict__ Wtl,
                 bf16* __restrict__ Wph, bf16* __restrict__ Wpl)
{
    const int bid = blockIdx.x, tid = threadIdx.x;
    if (bid < 1024) {
        const int i = bid * 256 + tid;
        float4 v = ((const float4*)x)[i];
        bsplit2(v.x, v.y, xh + i * 4,     xl + i * 4);
        bsplit2(v.z, v.w, xh + i * 4 + 2, xl + i * 4 + 2);
    } else if (bid < 2048) {
        const int widx = bid - 1024;
        const int z = widx >> 8, tile = widx & 255;
        const int k0 = (tile >> 4) * 32, n0 = (tile & 15) * 32;
        const float* W = z == 0 ? W0 : z == 1 ? W1 : z == 2 ? W2 : W3;
        __shared__ float t[32][33];
        #pragma unroll
        for (int j = 0; j < 4; j++) {
            const int r = (tid >> 5) + j * 8;
            t[r][tid & 31] = W[(long)(k0 + r) * 512 + n0 + (tid & 31)];
        }
        __syncthreads();
        #pragma unroll
        for (int j = 0; j < 4; j++) {
            const int nr = (tid >> 5) + j * 8, kc = tid & 31;
            const float v = t[kc][nr];
            const long o = (long)z * 262144 + (long)(n0 + nr) * 512 + k0 + kc;
            bf16 h = __float2bfloat16(v);
            Wth[o] = h;
            Wtl[o] = __float2bfloat16(v - __bfloat162float(h));
        }
    } else {
        const int widx = bid - 2048;
        const int z = widx >> 5, tile = widx & 31;
        const int k0 = (tile >> 1) * 32, n0 = (tile & 1) * 32;
        const float* W = z ? Wq2 : Wk2;
        __shared__ float t[32][33];
        #pragma unroll
        for (int j = 0; j < 4; j++) {
            const int r = (tid >> 5) + j * 8;
            t[r][tid & 31] = W[(long)(k0 + r) * 64 + n0 + (tid & 31)];
        }
        __syncthreads();
        #pragma unroll
        for (int j = 0; j < 4; j++) {
            const int nr = (tid >> 5) + j * 8, kc = tid & 31;
            const float v = t[kc][nr];
            const long o = (long)(z * 64 + n0 + nr) * 512 + k0 + kc;
            bf16 h = __float2bfloat16(v);
            Wph[o] = h;
            Wpl[o] = __float2bfloat16(v - __bfloat162float(h));
        }
    }
}

// ================= prefix (batched loads, MLP=16) ==========================
__global__ __launch_bounds__(256)
void prefix_kernel(const float4* __restrict__ S, bf16* __restrict__ Ph,
                   bf16* __restrict__ Pl)
{
    GDS();
    int gidx = blockIdx.x * 256 + threadIdx.x;
    int b = gidx >> 14;
    int i = gidx & 16383;
    long base = (long)b * 16 * 16384 + i;

    // batch all 16 chunk loads (independent -> MLP=16)
    float4 v[16];
    #pragma unroll
    for (int c = 0; c < 16; c++)
        v[c] = S[base + (long)c * 16384];

    float4 run = make_float4(0.f, 0.f, 0.f, 0.f);
    #pragma unroll
    for (int c = 0; c < 16; c++) {
        long e = (base + (long)c * 16384) * 4;
        bsplit2(run.x, run.y, Ph + e,     Pl + e);
        bsplit2(run.z, run.w, Ph + e + 2, Pl + e + 2);
        run.x += v[c].x; run.y += v[c].y; run.z += v[c].z; run.w += v[c].w;
    }
}

// ================= LayerNorm (warp-per-row) ================================
__global__ __launch_bounds__(256)
void ln_kernel(const float* __restrict__ X, const float* __restrict__ gg,
               const float* __restrict__ bb, bf16* __restrict__ oh,
               bf16* __restrict__ ol)
{
    GDS();
    const int row = blockIdx.x * 8 + (threadIdx.x >> 5);
    const int lane = threadIdx.x & 31;
    const float4* Xr = (const float4*)(X + (long)row * 512);
    float4 v[4];
    float s = 0.f, sq = 0.f;
    #pragma unroll
    for (int q = 0; q < 4; q++) {
        v[q] = Xr[lane + 32 * q];
        s  += v[q].x + v[q].y + v[q].z + v[q].w;
        sq += v[q].x * v[q].x + v[q].y * v[q].y + v[q].z * v[q].z + v[q].w * v[q].w;
    }
    #pragma unroll
    for (int o = 16; o; o >>= 1) {
        s  += __shfl_xor_sync(0xFFFFFFFFu, s, o);
        sq += __shfl_xor_sync(0xFFFFFFFFu, sq, o);
    }
    const float mean = s * (1.0f / 512.0f);
    const float var  = sq * (1.0f / 512.0f) - mean * mean;
    const float rs   = rsqrtf(var + 1e-5f);
    #pragma unroll
    for (int q = 0; q < 4; q++) {
        const int idx = lane + 32 * q;
        float4 g4 = ((const float4*)gg)[idx];
        float4 b4 = ((const float4*)bb)[idx];
        float o0 = (v[q].x - mean) * rs * g4.x + b4.x;
        float o1 = (v[q].y - mean) * rs * g4.y + b4.y;
        float o2 = (v[q].z - mean) * rs * g4.z + b4.z;
        float o3 = (v[q].w - mean) * rs * g4.w + b4.w;
        long e = (long)row * 512 + idx * 4;
        bsplit2(o0, o1, oh + e,     ol + e);
        bsplit2(o2, o3, oh + e + 2, ol + e + 2);
    }
}

// ================= PDL launch helper =======================================
template<typename F, typename... Args>
static inline void pdl_launch(F* k, dim3 g, dim3 b, size_t sm, Args... a) {
    cudaLaunchConfig_t cfg = {};
    cfg.gridDim = g; cfg.blockDim = b; cfg.dynamicSmemBytes = sm; cfg.stream = 0;
    cudaLaunchAttribute at[1];
    at[0].id = cudaLaunchAttributeProgrammaticStreamSerialization;
    at[0].val.programmaticStreamSerializationAllowed = 1;
    cfg.attrs = at; cfg.numAttrs = 1;
    cudaLaunchKernelEx(&cfg, k, a...);
}

// ================= launch =================
extern "C" void kernel_launch(void* const* d_in, const int* in_sizes, int n_in,
                              void* d_out, int out_size)
{
    const float* x    = (const float*)d_in[0];
    const float* Wk1  = (const float*)d_in[1];
    const float* bk1  = (const float*)d_in[2];
    const float* Wk2  = (const float*)d_in[3];
    const float* bk2  = (const float*)d_in[4];
    const float* Wq1  = (const float*)d_in[5];
    const float* bq1  = (const float*)d_in[6];
    const float* Wq2  = (const float*)d_in[7];
    const float* bq2  = (const float*)d_in[8];
    const float* Wv   = (const float*)d_in[9];
    const float* bv   = (const float*)d_in[10];
    const float* ln_g = (const float*)d_in[11];
    const float* ln_b = (const float*)d_in[12];
    const float* Wo   = (const float*)d_in[13];
    const float* bo   = (const float*)d_in[14];
    float* out = (float*)d_out;

    void* p;
    cudaGetSymbolAddress(&p, g_xh);    bf16* xh    = (bf16*)p;
    cudaGetSymbolAddress(&p, g_xl);    bf16* xl    = (bf16*)p;
    cudaGetSymbolAddress(&p, g_Wth);   bf16* Wth   = (bf16*)p;
    cudaGetSymbolAddress(&p, g_Wtl);   bf16* Wtl   = (bf16*)p;
    cudaGetSymbolAddress(&p, g_Wph);   bf16* Wph   = (bf16*)p;
    cudaGetSymbolAddress(&p, g_Wpl);   bf16* Wpl   = (bf16*)p;
    cudaGetSymbolAddress(&p, g_Hkh);   bf16* Hkh   = (bf16*)p;
    cudaGetSymbolAddress(&p, g_Hkl);   bf16* Hkl   = (bf16*)p;
    cudaGetSymbolAddress(&p, g_Hqh);   bf16* Hqh   = (bf16*)p;
    cudaGetSymbolAddress(&p, g_Hql);   bf16* Hql   = (bf16*)p;
    cudaGetSymbolAddress(&p, g_Vh);    bf16* Vh    = (bf16*)p;
    cudaGetSymbolAddress(&p, g_Vl);    bf16* Vl    = (bf16*)p;
    cudaGetSymbolAddress(&p, g_CSkh);  bf16* CSkh  = (bf16*)p;
    cudaGetSymbolAddress(&p, g_CSkl);  bf16* CSkl  = (bf16*)p;
    cudaGetSymbolAddress(&p, g_CSqh);  bf16* CSqh  = (bf16*)p;
    cudaGetSymbolAddress(&p, g_CSql);  bf16* CSql  = (bf16*)p;
    cudaGetSymbolAddress(&p, g_CSkTh); bf16* CSkTh = (bf16*)p;
    cudaGetSymbolAddress(&p, g_CSkTl); bf16* CSkTl = (bf16*)p;
    cudaGetSymbolAddress(&p, g_Ach);   bf16* Ach   = (bf16*)p;
    cudaGetSymbolAddress(&p, g_Acl);   bf16* Acl   = (bf16*)p;
    cudaGetSymbolAddress(&p, g_S);     float* S    = (float*)p;
    cudaGetSymbolAddress(&p, g_Ph);    bf16* Ph    = (bf16*)p;
    cudaGetSymbolAddress(&p, g_Pl);    bf16* Pl    = (bf16*)p;
    cudaGetSymbolAddress(&p, g_R);     float* R    = (float*)p;
    cudaGetSymbolAddress(&p, g_LNh);   bf16* LNh   = (bf16*)p;
    cudaGetSymbolAddress(&p, g_LNl);   bf16* LNl   = (bf16*)p;

    static int attr_set = 0;
    if (!attr_set) {
        cudaFuncSetAttribute(mma_gemm<0>, cudaFuncAttributeMaxDynamicSharedMemorySize, X0_SMEM);
        cudaFuncSetAttribute(mma_gemm<1>, cudaFuncAttributeMaxDynamicSharedMemorySize, X1_SMEM);
        cudaFuncSetAttribute(phase_mma,   cudaFuncAttributeMaxDynamicSharedMemorySize, P_SMEM);
        cudaFuncSetAttribute(sac_mma,    cudaFuncAttributeMaxDynamicSharedMemorySize, SAC_SMEM);
        cudaFuncSetAttribute(r_mma,      cudaFuncAttributeMaxDynamicSharedMemorySize, R_SMEM);
        attr_set = 1;
    }

    // 0) conversions (plain launch)
    prep_kernel<<<2112, 256>>>(x, Wk1, Wq1, Wv, Wo, Wk2, Wq2,
                               xh, xl, Wth, Wtl, Wph, Wpl);

    // 1) XW: Hk(gelu), Hq(gelu), V(bias). grid (4,32,3)=384.
    pdl_launch(mma_gemm<0>, dim3(4,32,3), dim3(128), (size_t)X0_SMEM,
        (const bf16*)xh, (const bf16*)xl, (const bf16*)Wth, (const bf16*)Wtl,
        bk1, bq1, bv, (const float*)nullptr,
        Hkh, Hkl, Hqh, Hql, Vh, Vl, (float*)nullptr);

    // 2) Phases (split-K, 32-row tiles). grid (1,64,2)=128.
    pdl_launch(phase_mma, dim3(1,64,2), dim3(256), (size_t)P_SMEM,
        (const bf16*)Hkh, (const bf16*)Hkl, (const bf16*)Hqh, (const bf16*)Hql,
        (const bf16*)Wph, (const bf16*)Wpl, bk2, bq2,
        CSkh, CSkl, CSqh, CSql, CSkTh, CSkTl);

    // 3) S + Ac. grid (9,1,32)=288.
    pdl_launch(sac_mma, dim3(9,1,32), dim3(256), (size_t)SAC_SMEM,
        (const bf16*)CSkTh, (const bf16*)CSkTl, (const bf16*)Vh, (const bf16*)Vl,
        (const bf16*)CSqh, (const bf16*)CSql, (const bf16*)CSkh, (const bf16*)CSkl,
        S, Ach, Acl);

    // 4) exclusive prefix -> split bf16 P (batched MLP=16 loads)
    pdl_launch(prefix_kernel, dim3(128), dim3(256), (size_t)0,
        (const float4*)S, Ph, Pl);

    // 5) R. grid (8,1,32)=256.
    pdl_launch(r_mma, dim3(8,1,32), dim3(128), (size_t)R_SMEM,
        (const bf16*)CSqh, (const bf16*)CSql, (const bf16*)Ach, (const bf16*)Acl,
        (const bf16*)Ph, (const bf16*)Pl, (const bf16*)Vh, (const bf16*)Vl, R);

    // 6) LN -> split bf16 (warp-per-row)
    pdl_launch(ln_kernel, dim3(256), dim3(256), (size_t)0,
        (const float*)R, ln_g, ln_b, LNh, LNl);

    // 7) out = x + LN @ Wo + bo. grid (8,32)=256.
    pdl_launch(mma_gemm<1>, dim3(8,32,1), dim3(128), (size_t)X1_SMEM,
        (const bf16*)LNh, (const bf16*)LNl,
        (const bf16*)(Wth + 3L*262144), (const bf16*)(Wtl + 3L*262144),
        bo, (const float*)nullptr, (const float*)nullptr, (const float*)x,
        (bf16*)nullptr, (bf16*)nullptr, (bf16*)nullptr, (bf16*)nullptr,
        (bf16*)nullptr, (bf16*)nullptr, out);
}